// round 1
// baseline (speedup 1.0000x reference)
#include <cuda_runtime.h>

#define BB      32
#define HH      8
#define WW2     32
#define PP      256          // HH*WW2
#define CF      512          // feature channels
#define AA      512          // attention units
#define RR      512          // rnn units
#define VV1     111
#define NSTEPS  31

// ---------------- device scratch (static: no allocations allowed) ----------------
__device__ float g_fp[(size_t)BB * PP * AA];   // feat_proj, layout [b][p][a]  (16.8 MB)
__device__ float g_x[(size_t)NSTEPS * BB * RR]; // teacher-forced embeddings [t][b][r]
__device__ float g_h0[2][BB * RR];
__device__ float g_h1[2][BB * RR];
__device__ float g_c0[BB * RR];
__device__ float g_c1[BB * RR];

__device__ __forceinline__ float tanh_fast(float x) {
    float y;
    asm("tanh.approx.f32 %0, %1;" : "=f"(y) : "f"(x));
    return y;
}

__device__ __forceinline__ float wredsum(float s) {
#pragma unroll
    for (int o = 16; o; o >>= 1) s += __shfl_xor_sync(0xffffffffu, s, o);
    return s;
}

// ---------------- init: zero states + precompute all step inputs ----------------
__global__ void k_init(const int* __restrict__ gt, const float* __restrict__ W_embed) {
    int idx = blockIdx.x * 256 + threadIdx.x;
    if (idx < BB * RR) {
        g_h0[0][idx] = 0.f;
        g_h1[0][idx] = 0.f;
        g_c0[idx] = 0.f;
        g_c1[idx] = 0.f;
    }
    if (idx < NSTEPS * BB * RR) {
        int t = idx / (BB * RR);
        int rem = idx - t * (BB * RR);
        int b = rem >> 9;
        int r = rem & 511;
        float v = 0.f;
        if (t > 0) {
            int g = gt[b * NSTEPS + t - 1];
            v = W_embed[r * VV1 + g];
        }
        g_x[idx] = v;
    }
}

// ---------------- conv3x3 SAME: feat_proj[b][p][a] ----------------
// grid (8 a-tiles, 2 p-tiles, 32 b), 256 threads; thread tile 4a x 8p; K chunked by 8 channels
__global__ void k_conv(const float* __restrict__ feat, const float* __restrict__ Wf,
                       const float* __restrict__ bf) {
    __shared__ float Ism[8][6 * 34];   // 8 ch x (4 rows + halo = 6) x (32 cols + halo = 34)
    __shared__ float Wsm[64][72];      // 64 out-ch x (8 ch * 9 taps)

    int b  = blockIdx.z;
    int a0 = blockIdx.x * 64;
    int r0 = blockIdx.y * 4;          // global output row base
    int tid = threadIdx.x;
    int tx = tid & 15, ty = tid >> 4;
    int plbase = tx * 8;
    int lrow = plbase >> 5;           // 0..3 (8-col groups never cross a row)
    int lcol = plbase & 31;

    float acc[4][8];
#pragma unroll
    for (int j = 0; j < 4; j++)
#pragma unroll
        for (int i = 0; i < 8; i++) acc[j][i] = 0.f;

    const float* fb = feat + (size_t)b * CF * PP;

    for (int c0 = 0; c0 < CF; c0 += 8) {
        __syncthreads();
        // stage input tile (zero padded halo)
        for (int i = tid; i < 8 * 204; i += 256) {
            int cc = i / 204;
            int rem = i - cc * 204;
            int rr = rem / 34;
            int col = rem - rr * 34;
            int y = r0 - 1 + rr;
            int x = col - 1;
            float v = 0.f;
            if (y >= 0 && y < HH && x >= 0 && x < WW2) v = fb[(c0 + cc) * PP + y * WW2 + x];
            Ism[cc][rem] = v;
        }
        // stage weight tile
        for (int i = tid; i < 64 * 72; i += 256) {
            int al = i / 72;
            int rem = i - al * 72;      // rem = cc*9 + tap
            int cc = rem / 9;
            int tp = rem - cc * 9;
            Wsm[al][rem] = Wf[((size_t)(a0 + al) * CF + (c0 + cc)) * 9 + tp];
        }
        __syncthreads();

#pragma unroll
        for (int cc = 0; cc < 8; cc++) {
#pragma unroll
            for (int ky = 0; ky < 3; ky++) {
                float iv[10];
                const float* ir = &Ism[cc][(lrow + ky) * 34 + lcol];
#pragma unroll
                for (int m = 0; m < 10; m++) iv[m] = ir[m];
#pragma unroll
                for (int kx = 0; kx < 3; kx++) {
                    float w0 = Wsm[ty * 4 + 0][cc * 9 + ky * 3 + kx];
                    float w1 = Wsm[ty * 4 + 1][cc * 9 + ky * 3 + kx];
                    float w2 = Wsm[ty * 4 + 2][cc * 9 + ky * 3 + kx];
                    float w3 = Wsm[ty * 4 + 3][cc * 9 + ky * 3 + kx];
#pragma unroll
                    for (int i2 = 0; i2 < 8; i2++) {
                        float f = iv[kx + i2];
                        acc[0][i2] += w0 * f;
                        acc[1][i2] += w1 * f;
                        acc[2][i2] += w2 * f;
                        acc[3][i2] += w3 * f;
                    }
                }
            }
        }
    }

    int p0 = (r0 + lrow) * WW2 + lcol;
#pragma unroll
    for (int j = 0; j < 4; j++) {
        float bv = bf[a0 + ty * 4 + j];
#pragma unroll
        for (int i2 = 0; i2 < 8; i2++) {
            g_fp[((size_t)b * PP + p0 + i2) * AA + a0 + ty * 4 + j] = acc[j][i2] + bv;
        }
    }
}

// ---------------- fused LSTM cell: thread (j,b) computes all 4 gates + h/c update --------
// grid 128 blocks x 128 threads; j = blk*4 + (tid>>5), b = tid&31
__global__ void k_lstm(int cell, int t,
                       const float* __restrict__ wih, const float* __restrict__ whh,
                       const float* __restrict__ bih, const float* __restrict__ bhh) {
    __shared__ float u[32 * 65];   // staged activation chunk [b][64] padded
    int tid = threadIdx.x;
    int b = tid & 31, jl = tid >> 5;
    int j = blockIdx.x * 4 + jl;
    int cur = t & 1, nxt = cur ^ 1;

    const float* xin = (cell == 0) ? &g_x[(size_t)t * BB * RR] : g_h0[nxt];
    const float* hin = (cell == 0) ? g_h0[cur] : g_h1[cur];
    float* hout = (cell == 0) ? g_h0[nxt] : g_h1[nxt];
    float* cst  = (cell == 0) ? g_c0 : g_c1;

    float ai = bih[j]        + bhh[j];
    float af = bih[512 + j]  + bhh[512 + j];
    float ag = bih[1024 + j] + bhh[1024 + j];
    float ao = bih[1536 + j] + bhh[1536 + j];

    for (int phase = 0; phase < 2; phase++) {
        const float* src = phase ? hin : xin;
        const float* W   = phase ? whh : wih;
        const float* wi = W + (size_t)j * 512;
        const float* wf = W + (size_t)(512 + j) * 512;
        const float* wg = W + (size_t)(1024 + j) * 512;
        const float* wo = W + (size_t)(1536 + j) * 512;

        for (int ch = 0; ch < 8; ch++) {
            __syncthreads();
            for (int i = tid; i < 512; i += 128) {
                int bb = i >> 4;
                int kq = (i & 15) << 2;
                float4 v = *(const float4*)&src[bb * 512 + ch * 64 + kq];
                float* d = &u[bb * 65 + kq];
                d[0] = v.x; d[1] = v.y; d[2] = v.z; d[3] = v.w;
            }
            __syncthreads();
            const float* ub = &u[b * 65];
            int kb = ch * 64;
#pragma unroll
            for (int kk = 0; kk < 64; kk += 4) {
                float4 vi = *(const float4*)&wi[kb + kk];
                float4 vf = *(const float4*)&wf[kb + kk];
                float4 vg = *(const float4*)&wg[kb + kk];
                float4 vo = *(const float4*)&wo[kb + kk];
                float u0 = ub[kk], u1 = ub[kk + 1], u2 = ub[kk + 2], u3 = ub[kk + 3];
                ai += vi.x * u0; af += vf.x * u0; ag += vg.x * u0; ao += vo.x * u0;
                ai += vi.y * u1; af += vf.y * u1; ag += vg.y * u1; ao += vo.y * u1;
                ai += vi.z * u2; af += vf.z * u2; ag += vg.z * u2; ao += vo.z * u2;
                ai += vi.w * u3; af += vf.w * u3; ag += vg.w * u3; ao += vo.w * u3;
            }
        }
    }

    float si = 1.f / (1.f + __expf(-ai));
    float sf = 1.f / (1.f + __expf(-af));
    float so = 1.f / (1.f + __expf(-ao));
    float tg = tanhf(ag);                 // accurate on the recurrent path
    int o = b * 512 + j;
    float cn = sf * cst[o] + si * tg;
    cst[o] = cn;
    hout[o] = so * tanhf(cn);
}

// ---------------- fused attention + output: one block per batch element ----------------
__global__ void k_attn(int t, const float* __restrict__ feat,
                       const float* __restrict__ Wst, const float* __restrict__ watt,
                       const float* __restrict__ Wout, const float* __restrict__ bout,
                       float* __restrict__ out) {
    __shared__ float h1s[512], sps[512], was[512], gls[512];
    __shared__ float att[256];
    __shared__ float redm[8], reds[8];

    int b = blockIdx.x, tid = threadIdx.x;
    int lane = tid & 31, w = tid >> 5;
    const float* h1 = g_h1[(t & 1) ^ 1];

    for (int i = tid; i < 512; i += 256) {
        h1s[i] = h1[b * 512 + i];
        was[i] = watt[i];
    }
    __syncthreads();

    // sp = h1 @ W_state^T   (warp per row, coalesced float4)
    for (int a = w; a < 512; a += 8) {
        const float4* wr = (const float4*)(Wst + (size_t)a * 512);
        float s = 0.f;
#pragma unroll
        for (int it = 0; it < 4; it++) {
            int k4 = lane + it * 32;
            float4 v = wr[k4];
            const float* hh = &h1s[k4 << 2];
            s += v.x * hh[0] + v.y * hh[1] + v.z * hh[2] + v.w * hh[3];
        }
        s = wredsum(s);
        if (lane == 0) sps[a] = s;
    }
    __syncthreads();

    // scores[p] = sum_a tanh(feat_proj + sp) * w_att
    for (int p = w; p < 256; p += 8) {
        const float4* fr = (const float4*)(g_fp + ((size_t)b * PP + p) * AA);
        float s = 0.f;
#pragma unroll
        for (int it = 0; it < 4; it++) {
            int k4 = lane + it * 32;
            float4 v = fr[k4];
            float4 sp4 = *(const float4*)&sps[k4 << 2];
            float4 wa4 = *(const float4*)&was[k4 << 2];
            s += tanh_fast(v.x + sp4.x) * wa4.x;
            s += tanh_fast(v.y + sp4.y) * wa4.y;
            s += tanh_fast(v.z + sp4.z) * wa4.z;
            s += tanh_fast(v.w + sp4.w) * wa4.w;
        }
        s = wredsum(s);
        if (lane == 0) att[p] = s;
    }
    __syncthreads();

    // softmax over 256 positions
    float xv = att[tid];
    float m = xv;
#pragma unroll
    for (int o = 16; o; o >>= 1) m = fmaxf(m, __shfl_xor_sync(0xffffffffu, m, o));
    if (lane == 0) redm[w] = m;
    __syncthreads();
    if (tid == 0) {
        float mm = redm[0];
        for (int i = 1; i < 8; i++) mm = fmaxf(mm, redm[i]);
        redm[0] = mm;
    }
    __syncthreads();
    float e = __expf(xv - redm[0]);
    float ssum = wredsum(e);
    if (lane == 0) reds[w] = ssum;
    __syncthreads();
    if (tid == 0) {
        float s2 = 0.f;
        for (int i = 0; i < 8; i++) s2 += reds[i];
        reds[0] = 1.f / s2;
    }
    __syncthreads();
    att[tid] = e * reds[0];
    __syncthreads();

    // glimpse[c] = sum_p features[b][c][p] * att[p]
    for (int c = w; c < 512; c += 8) {
        const float4* fr = (const float4*)(feat + ((size_t)b * CF + c) * PP);
        float s = 0.f;
#pragma unroll
        for (int it = 0; it < 2; it++) {
            int p4 = lane + it * 32;
            float4 v = fr[p4];
            float4 a4 = *(const float4*)&att[p4 << 2];
            s += v.x * a4.x + v.y * a4.y + v.z * a4.z + v.w * a4.w;
        }
        s = wredsum(s);
        if (lane == 0) gls[c] = s;
    }
    __syncthreads();

    // logits = [h1, glimpse] @ W_out^T + b_out
    for (int vI = w; vI < VV1; vI += 8) {
        const float4* wr = (const float4*)(Wout + (size_t)vI * 1024);
        float s = 0.f;
#pragma unroll
        for (int it = 0; it < 8; it++) {
            int k4 = lane + it * 32;
            float4 v = wr[k4];
            const float* sv = (k4 < 128) ? &h1s[k4 << 2] : &gls[(k4 - 128) << 2];
            s += v.x * sv[0] + v.y * sv[1] + v.z * sv[2] + v.w * sv[3];
        }
        s = wredsum(s);
        if (lane == 0) out[((size_t)b * NSTEPS + t) * VV1 + vI] = s + bout[vI];
    }
}

// ---------------- launch ----------------
extern "C" void kernel_launch(void* const* d_in, const int* in_sizes, int n_in,
                              void* d_out, int out_size) {
    (void)in_sizes; (void)n_in; (void)out_size;
    const float* features = (const float*)d_in[0];
    const int*   gt       = (const int*)d_in[2];
    const float* W_feat   = (const float*)d_in[3];
    const float* b_feat   = (const float*)d_in[4];
    const float* W_state  = (const float*)d_in[5];
    const float* w_att    = (const float*)d_in[6];
    const float* W_embed  = (const float*)d_in[7];
    const float* wih0     = (const float*)d_in[8];
    const float* whh0     = (const float*)d_in[9];
    const float* bih0     = (const float*)d_in[10];
    const float* bhh0     = (const float*)d_in[11];
    const float* wih1     = (const float*)d_in[12];
    const float* whh1     = (const float*)d_in[13];
    const float* bih1     = (const float*)d_in[14];
    const float* bhh1     = (const float*)d_in[15];
    const float* W_out    = (const float*)d_in[16];
    const float* b_out    = (const float*)d_in[17];
    float* out = (float*)d_out;

    k_init<<<1984, 256>>>(gt, W_embed);
    k_conv<<<dim3(8, 2, 32), 256>>>(features, W_feat, b_feat);

    for (int t = 0; t < NSTEPS; t++) {
        k_lstm<<<128, 128>>>(0, t, wih0, whh0, bih0, bhh0);
        k_lstm<<<128, 128>>>(1, t, wih1, whh1, bih1, bhh1);
        k_attn<<<32, 256>>>(t, features, W_state, w_att, W_out, b_out, out);
    }
}

// round 2
// speedup vs baseline: 1.7877x; 1.7877x over previous
#include <cuda_runtime.h>

#define BB      32
#define HH      8
#define WW2     32
#define PP      256          // HH*WW2
#define CF      512          // feature channels
#define AA      512          // attention units
#define RR      512          // rnn units
#define VV1     111
#define NSTEPS  31

// ---------------- device scratch (static: no allocations allowed) ----------------
__device__ float g_fp[(size_t)BB * PP * AA];   // feat_proj, layout [b][p][a]  (16.8 MB)
__device__ float g_x[(size_t)NSTEPS * BB * RR]; // teacher-forced embeddings [t][b][r]
__device__ float g_h0[2][BB * RR];
__device__ float g_h1[2][BB * RR];
__device__ float g_c0[BB * RR];
__device__ float g_c1[BB * RR];

__device__ __forceinline__ float tanh_fast(float x) {
    float y;
    asm("tanh.approx.f32 %0, %1;" : "=f"(y) : "f"(x));
    return y;
}

__device__ __forceinline__ float wredsum(float s) {
#pragma unroll
    for (int o = 16; o; o >>= 1) s += __shfl_xor_sync(0xffffffffu, s, o);
    return s;
}

// ---------------- init: zero states + precompute all step inputs ----------------
__global__ void k_init(const int* __restrict__ gt, const float* __restrict__ W_embed) {
    int idx = blockIdx.x * 256 + threadIdx.x;
    if (idx < BB * RR) {
        g_h0[0][idx] = 0.f;
        g_h1[0][idx] = 0.f;
        g_c0[idx] = 0.f;
        g_c1[idx] = 0.f;
    }
    if (idx < NSTEPS * BB * RR) {
        int t = idx / (BB * RR);
        int rem = idx - t * (BB * RR);
        int b = rem >> 9;
        int r = rem & 511;
        float v = 0.f;
        if (t > 0) {
            int g = gt[b * NSTEPS + t - 1];
            v = W_embed[r * VV1 + g];
        }
        g_x[idx] = v;
    }
}

// ---------------- conv3x3 SAME: feat_proj[b][p][a] ----------------
// grid (8 a-tiles, 2 p-tiles, 32 b), 256 threads; thread tile 4a x 8p; K chunked by 8 channels
__global__ void k_conv(const float* __restrict__ feat, const float* __restrict__ Wf,
                       const float* __restrict__ bf) {
    __shared__ float Ism[8][6 * 34];   // 8 ch x (4 rows + halo = 6) x (32 cols + halo = 34)
    __shared__ float Wsm[64][72];      // 64 out-ch x (8 ch * 9 taps)

    int b  = blockIdx.z;
    int a0 = blockIdx.x * 64;
    int r0 = blockIdx.y * 4;          // global output row base
    int tid = threadIdx.x;
    int tx = tid & 15, ty = tid >> 4;
    int plbase = tx * 8;
    int lrow = plbase >> 5;           // 0..3 (8-col groups never cross a row)
    int lcol = plbase & 31;

    float acc[4][8];
#pragma unroll
    for (int j = 0; j < 4; j++)
#pragma unroll
        for (int i = 0; i < 8; i++) acc[j][i] = 0.f;

    const float* fb = feat + (size_t)b * CF * PP;

    for (int c0 = 0; c0 < CF; c0 += 8) {
        __syncthreads();
        // stage input tile (zero padded halo)
        for (int i = tid; i < 8 * 204; i += 256) {
            int cc = i / 204;
            int rem = i - cc * 204;
            int rr = rem / 34;
            int col = rem - rr * 34;
            int y = r0 - 1 + rr;
            int x = col - 1;
            float v = 0.f;
            if (y >= 0 && y < HH && x >= 0 && x < WW2) v = fb[(c0 + cc) * PP + y * WW2 + x];
            Ism[cc][rem] = v;
        }
        // stage weight tile
        for (int i = tid; i < 64 * 72; i += 256) {
            int al = i / 72;
            int rem = i - al * 72;      // rem = cc*9 + tap
            int cc = rem / 9;
            int tp = rem - cc * 9;
            Wsm[al][rem] = Wf[((size_t)(a0 + al) * CF + (c0 + cc)) * 9 + tp];
        }
        __syncthreads();

#pragma unroll
        for (int cc = 0; cc < 8; cc++) {
#pragma unroll
            for (int ky = 0; ky < 3; ky++) {
                float iv[10];
                const float* ir = &Ism[cc][(lrow + ky) * 34 + lcol];
#pragma unroll
                for (int m = 0; m < 10; m++) iv[m] = ir[m];
#pragma unroll
                for (int kx = 0; kx < 3; kx++) {
                    float w0 = Wsm[ty * 4 + 0][cc * 9 + ky * 3 + kx];
                    float w1 = Wsm[ty * 4 + 1][cc * 9 + ky * 3 + kx];
                    float w2 = Wsm[ty * 4 + 2][cc * 9 + ky * 3 + kx];
                    float w3 = Wsm[ty * 4 + 3][cc * 9 + ky * 3 + kx];
#pragma unroll
                    for (int i2 = 0; i2 < 8; i2++) {
                        float f = iv[kx + i2];
                        acc[0][i2] += w0 * f;
                        acc[1][i2] += w1 * f;
                        acc[2][i2] += w2 * f;
                        acc[3][i2] += w3 * f;
                    }
                }
            }
        }
    }

    int p0 = (r0 + lrow) * WW2 + lcol;
#pragma unroll
    for (int j = 0; j < 4; j++) {
        float bv = bf[a0 + ty * 4 + j];
#pragma unroll
        for (int i2 = 0; i2 < 8; i2++) {
            g_fp[((size_t)b * PP + p0 + i2) * AA + a0 + ty * 4 + j] = acc[j][i2] + bv;
        }
    }
}

// ---------------- LSTM cell v2: one thread per (unit, gate, batch) ----------------
// grid 256 blocks x 256 threads. Block covers 2 units x 4 gates x 32 batch.
// Weights + activations staged through smem with coalesced loads / conflict-free LDS.
__global__ void __launch_bounds__(256) k_lstm(int cell, int t,
                       const float* __restrict__ wih, const float* __restrict__ whh,
                       const float* __restrict__ bih, const float* __restrict__ bhh) {
    __shared__ float acts[32 * 132];    // [b][k] row stride 132 (conflict-free LDS.128)
    __shared__ float ws[8 * 128];       // [row r][k]   r = jl*4 + g
    __shared__ float gbuf[8][33];       // gate pre-activations [r][b]

    int tid = threadIdx.x;
    int b = tid & 31;
    int r = tid >> 5;              // 0..7
    int jl = r >> 2, g = r & 3;
    int j0 = blockIdx.x * 2;
    int grow = g * 512 + j0 + jl;  // global gate row

    int cur = t & 1, nxt = cur ^ 1;
    const float* xin = (cell == 0) ? &g_x[(size_t)t * BB * RR] : g_h0[nxt];
    const float* hin = (cell == 0) ? g_h0[cur] : g_h1[cur];
    float* hout = (cell == 0) ? g_h0[nxt] : g_h1[nxt];
    float* cst  = (cell == 0) ? g_c0 : g_c1;

    float acc = bih[grow] + bhh[grow];

    // staging thread mapping
    int sb = tid >> 3;             // 0..31: batch row for act staging
    int sm = tid & 7;              // 0..7 : float4 slot
    int wrow = tid >> 5;           // 0..7 : weight row
    int wm = tid & 31;             // 0..31: float4 within row
    int wjl = wrow >> 2, wg = wrow & 3;

    for (int ch = 0; ch < 8; ch++) {
        const float* src; const float* W; int col0;
        if (ch < 4) { src = xin; W = wih; col0 = ch * 128; }
        else        { src = hin; W = whh; col0 = (ch - 4) * 128; }
        __syncthreads();
        // stage activations: 32 b x 128 k
        {
            const float* srow = src + sb * 512 + col0;
            float* arow = acts + sb * 132;
#pragma unroll
            for (int q = 0; q < 4; q++) {
                int k4 = (sm + 8 * q) << 2;
                *(float4*)&arow[k4] = *(const float4*)&srow[k4];
            }
        }
        // stage weights: 8 rows x 128 k
        {
            const float* Wr = W + (size_t)(wg * 512 + j0 + wjl) * 512 + col0;
            *(float4*)&ws[wrow * 128 + (wm << 2)] = *(const float4*)&Wr[wm << 2];
        }
        __syncthreads();

        const float* ab = acts + b * 132;
        const float* wb = ws + r * 128;
#pragma unroll
        for (int kk = 0; kk < 128; kk += 4) {
            float4 a4 = *(const float4*)&ab[kk];
            float4 w4 = *(const float4*)&wb[kk];    // warp-uniform -> broadcast
            acc += a4.x * w4.x + a4.y * w4.y + a4.z * w4.z + a4.w * w4.w;
        }
    }

    gbuf[r][b] = acc;
    __syncthreads();

    if (tid < 64) {
        int ejl = tid >> 5, eb = tid & 31;
        float ai = gbuf[ejl * 4 + 0][eb];
        float af = gbuf[ejl * 4 + 1][eb];
        float ag = gbuf[ejl * 4 + 2][eb];
        float ao = gbuf[ejl * 4 + 3][eb];
        float si = 1.f / (1.f + __expf(-ai));
        float sf = 1.f / (1.f + __expf(-af));
        float so = 1.f / (1.f + __expf(-ao));
        float tg = tanhf(ag);
        int o = eb * 512 + j0 + ejl;
        float cn = sf * cst[o] + si * tg;
        cst[o] = cn;
        hout[o] = so * tanhf(cn);
    }
}

// ---------------- fused attention + output: one block (512 thr) per batch element --------
__global__ void __launch_bounds__(512) k_attn(int t, const float* __restrict__ feat,
                       const float* __restrict__ Wst, const float* __restrict__ watt,
                       const float* __restrict__ Wout, const float* __restrict__ bout,
                       float* __restrict__ out) {
    __shared__ float h1s[512], sps[512], was[512], gls[512];
    __shared__ float att[256];
    __shared__ float redm[8], reds[8];

    int b = blockIdx.x, tid = threadIdx.x;
    int lane = tid & 31, w = tid >> 5;       // 16 warps
    const float* h1 = g_h1[(t & 1) ^ 1];

    for (int i = tid; i < 512; i += 512) {
        h1s[i] = h1[b * 512 + i];
        was[i] = watt[i];
    }
    __syncthreads();

    // sp = h1 @ W_state^T   (warp per row, coalesced float4)
    for (int a = w; a < 512; a += 16) {
        const float4* wr = (const float4*)(Wst + (size_t)a * 512);
        float s = 0.f;
#pragma unroll
        for (int it = 0; it < 4; it++) {
            int k4 = lane + it * 32;
            float4 v = wr[k4];
            const float* hh = &h1s[k4 << 2];
            s += v.x * hh[0] + v.y * hh[1] + v.z * hh[2] + v.w * hh[3];
        }
        s = wredsum(s);
        if (lane == 0) sps[a] = s;
    }
    __syncthreads();

    // scores[p] = sum_a tanh(feat_proj + sp) * w_att
    for (int p = w; p < 256; p += 16) {
        const float4* fr = (const float4*)(g_fp + ((size_t)b * PP + p) * AA);
        float s = 0.f;
#pragma unroll
        for (int it = 0; it < 4; it++) {
            int k4 = lane + it * 32;
            float4 v = fr[k4];
            float4 sp4 = *(const float4*)&sps[k4 << 2];
            float4 wa4 = *(const float4*)&was[k4 << 2];
            s += tanh_fast(v.x + sp4.x) * wa4.x;
            s += tanh_fast(v.y + sp4.y) * wa4.y;
            s += tanh_fast(v.z + sp4.z) * wa4.z;
            s += tanh_fast(v.w + sp4.w) * wa4.w;
        }
        s = wredsum(s);
        if (lane == 0) att[p] = s;
    }
    __syncthreads();

    // softmax over 256 positions (first 8 warps participate)
    if (tid < 256) {
        float xv = att[tid];
        float m = xv;
#pragma unroll
        for (int o = 16; o; o >>= 1) m = fmaxf(m, __shfl_xor_sync(0xffffffffu, m, o));
        if (lane == 0) redm[w] = m;
    }
    __syncthreads();
    if (tid == 0) {
        float mm = redm[0];
        for (int i = 1; i < 8; i++) mm = fmaxf(mm, redm[i]);
        redm[0] = mm;
    }
    __syncthreads();
    if (tid < 256) {
        float e = __expf(att[tid] - redm[0]);
        float ssum = wredsum(e);
        if (lane == 0) reds[w] = ssum;
        att[tid] = e;   // store unnormalized; rescale below
    }
    __syncthreads();
    if (tid == 0) {
        float s2 = 0.f;
        for (int i = 0; i < 8; i++) s2 += reds[i];
        reds[0] = 1.f / s2;
    }
    __syncthreads();
    if (tid < 256) att[tid] = att[tid] * reds[0];
    __syncthreads();

    // glimpse[c] = sum_p features[b][c][p] * att[p]
    for (int c = w; c < 512; c += 16) {
        const float4* fr = (const float4*)(feat + ((size_t)b * CF + c) * PP);
        float s = 0.f;
#pragma unroll
        for (int it = 0; it < 2; it++) {
            int p4 = lane + it * 32;
            float4 v = fr[p4];
            float4 a4 = *(const float4*)&att[p4 << 2];
            s += v.x * a4.x + v.y * a4.y + v.z * a4.z + v.w * a4.w;
        }
        s = wredsum(s);
        if (lane == 0) gls[c] = s;
    }
    __syncthreads();

    // logits = [h1, glimpse] @ W_out^T + b_out
    for (int vI = w; vI < VV1; vI += 16) {
        const float4* wr = (const float4*)(Wout + (size_t)vI * 1024);
        float s = 0.f;
#pragma unroll
        for (int it = 0; it < 8; it++) {
            int k4 = lane + it * 32;
            float4 v = wr[k4];
            const float* sv = (k4 < 128) ? &h1s[k4 << 2] : &gls[(k4 - 128) << 2];
            s += v.x * sv[0] + v.y * sv[1] + v.z * sv[2] + v.w * sv[3];
        }
        s = wredsum(s);
        if (lane == 0) out[((size_t)b * NSTEPS + t) * VV1 + vI] = s + bout[vI];
    }
}

// ---------------- launch ----------------
extern "C" void kernel_launch(void* const* d_in, const int* in_sizes, int n_in,
                              void* d_out, int out_size) {
    (void)in_sizes; (void)n_in; (void)out_size;
    const float* features = (const float*)d_in[0];
    const int*   gt       = (const int*)d_in[2];
    const float* W_feat   = (const float*)d_in[3];
    const float* b_feat   = (const float*)d_in[4];
    const float* W_state  = (const float*)d_in[5];
    const float* w_att    = (const float*)d_in[6];
    const float* W_embed  = (const float*)d_in[7];
    const float* wih0     = (const float*)d_in[8];
    const float* whh0     = (const float*)d_in[9];
    const float* bih0     = (const float*)d_in[10];
    const float* bhh0     = (const float*)d_in[11];
    const float* wih1     = (const float*)d_in[12];
    const float* whh1     = (const float*)d_in[13];
    const float* bih1     = (const float*)d_in[14];
    const float* bhh1     = (const float*)d_in[15];
    const float* W_out    = (const float*)d_in[16];
    const float* b_out    = (const float*)d_in[17];
    float* out = (float*)d_out;

    k_init<<<1984, 256>>>(gt, W_embed);
    k_conv<<<dim3(8, 2, 32), 256>>>(features, W_feat, b_feat);

    for (int t = 0; t < NSTEPS; t++) {
        k_lstm<<<256, 256>>>(0, t, wih0, whh0, bih0, bhh0);
        k_lstm<<<256, 256>>>(1, t, wih1, whh1, bih1, bhh1);
        k_attn<<<32, 512>>>(t, features, W_state, w_att, W_out, b_out, out);
    }
}

// round 3
// speedup vs baseline: 2.1011x; 1.1753x over previous
#include <cuda_runtime.h>

#define BB      32
#define HH      8
#define WW2     32
#define PP      256
#define CF      512
#define AA      512
#define RR      512
#define VV1     111
#define NSTEPS  31
#define NBLK    128
#define NTHR    256

// ---------------- device scratch ----------------
__device__ float g_fp[(size_t)BB * PP * AA];    // feat_proj [b][p][a]
__device__ float g_x[(size_t)NSTEPS * BB * RR]; // embeddings [t][b][r]
__device__ float g_h0[2][BB * RR];
__device__ float g_h1[2][BB * RR];
__device__ float g_c0[BB * RR];
__device__ float g_c1[BB * RR];
__device__ float g_sp[BB * AA];                 // state projection per step
__device__ float g_glp[(size_t)BB * 4 * CF];    // partial glimpse [b][psub][c]
__device__ float g_psum[BB * 4];                // partial exp sums
__device__ unsigned g_cnt;
__device__ unsigned g_gen;

__device__ __forceinline__ float tanh_fast(float x) {
    float y;
    asm("tanh.approx.f32 %0, %1;" : "=f"(y) : "f"(x));
    return y;
}

__device__ __forceinline__ float wredsum(float s) {
#pragma unroll
    for (int o = 16; o; o >>= 1) s += __shfl_xor_sync(0xffffffffu, s, o);
    return s;
}

__device__ __forceinline__ void grid_bar(unsigned ep) {
    __syncthreads();
    if (threadIdx.x == 0) {
        __threadfence();
        unsigned old = atomicAdd(&g_cnt, 1u);
        if (old == NBLK - 1) {
            g_cnt = 0;
            __threadfence();
            *(volatile unsigned*)&g_gen = ep;
        } else {
            while (*(volatile unsigned*)&g_gen < ep) __nanosleep(64);
        }
        __threadfence();
    }
    __syncthreads();
}

// ---------------- init ----------------
__global__ void k_init(const int* __restrict__ gt, const float* __restrict__ W_embed) {
    int idx = blockIdx.x * 256 + threadIdx.x;
    if (idx == 0) { g_cnt = 0; g_gen = 0; }
    if (idx < BB * RR) {
        g_h0[0][idx] = 0.f;
        g_h1[0][idx] = 0.f;
        g_c0[idx] = 0.f;
        g_c1[idx] = 0.f;
    }
    if (idx < NSTEPS * BB * RR) {
        int t = idx / (BB * RR);
        int rem = idx - t * (BB * RR);
        int b = rem >> 9;
        int r = rem & 511;
        float v = 0.f;
        if (t > 0) {
            int g = gt[b * NSTEPS + t - 1];
            v = W_embed[r * VV1 + g];
        }
        g_x[idx] = v;
    }
}

// ---------------- conv3x3 SAME (unchanged, fp32 FFMA roofline) ----------------
__global__ void k_conv(const float* __restrict__ feat, const float* __restrict__ Wf,
                       const float* __restrict__ bf) {
    __shared__ float Ism[8][6 * 34];
    __shared__ float Wsm[64][72];

    int b  = blockIdx.z;
    int a0 = blockIdx.x * 64;
    int r0 = blockIdx.y * 4;
    int tid = threadIdx.x;
    int tx = tid & 15, ty = tid >> 4;
    int plbase = tx * 8;
    int lrow = plbase >> 5;
    int lcol = plbase & 31;

    float acc[4][8];
#pragma unroll
    for (int j = 0; j < 4; j++)
#pragma unroll
        for (int i = 0; i < 8; i++) acc[j][i] = 0.f;

    const float* fb = feat + (size_t)b * CF * PP;

    for (int c0 = 0; c0 < CF; c0 += 8) {
        __syncthreads();
        for (int i = tid; i < 8 * 204; i += 256) {
            int cc = i / 204;
            int rem = i - cc * 204;
            int rr = rem / 34;
            int col = rem - rr * 34;
            int y = r0 - 1 + rr;
            int x = col - 1;
            float v = 0.f;
            if (y >= 0 && y < HH && x >= 0 && x < WW2) v = fb[(c0 + cc) * PP + y * WW2 + x];
            Ism[cc][rem] = v;
        }
        for (int i = tid; i < 64 * 72; i += 256) {
            int al = i / 72;
            int rem = i - al * 72;
            int cc = rem / 9;
            int tp = rem - cc * 9;
            Wsm[al][rem] = Wf[((size_t)(a0 + al) * CF + (c0 + cc)) * 9 + tp];
        }
        __syncthreads();

#pragma unroll
        for (int cc = 0; cc < 8; cc++) {
#pragma unroll
            for (int ky = 0; ky < 3; ky++) {
                float iv[10];
                const float* ir = &Ism[cc][(lrow + ky) * 34 + lcol];
#pragma unroll
                for (int m = 0; m < 10; m++) iv[m] = ir[m];
#pragma unroll
                for (int kx = 0; kx < 3; kx++) {
                    float w0 = Wsm[ty * 4 + 0][cc * 9 + ky * 3 + kx];
                    float w1 = Wsm[ty * 4 + 1][cc * 9 + ky * 3 + kx];
                    float w2 = Wsm[ty * 4 + 2][cc * 9 + ky * 3 + kx];
                    float w3 = Wsm[ty * 4 + 3][cc * 9 + ky * 3 + kx];
#pragma unroll
                    for (int i2 = 0; i2 < 8; i2++) {
                        float f = iv[kx + i2];
                        acc[0][i2] += w0 * f;
                        acc[1][i2] += w1 * f;
                        acc[2][i2] += w2 * f;
                        acc[3][i2] += w3 * f;
                    }
                }
            }
        }
    }

    int p0 = (r0 + lrow) * WW2 + lcol;
#pragma unroll
    for (int j = 0; j < 4; j++) {
        float bv = bf[a0 + ty * 4 + j];
#pragma unroll
        for (int i2 = 0; i2 < 8; i2++) {
            g_fp[((size_t)b * PP + p0 + i2) * AA + a0 + ty * 4 + j] = acc[j][i2] + bv;
        }
    }
}

// ---------------- persistent decode: all 31 steps, weights resident in smem ----------------
// 128 blocks x 256 threads, 1 block/SM. Block owns units [4*blk, 4*blk+4) for BOTH cells.
// Attention identity: b = blk & 31, psub = blk >> 5 (4 blocks per batch element).
__global__ void __launch_bounds__(NTHR) k_decode(
    const float* __restrict__ feat,
    const float* __restrict__ wih0, const float* __restrict__ whh0,
    const float* __restrict__ bih0, const float* __restrict__ bhh0,
    const float* __restrict__ wih1, const float* __restrict__ whh1,
    const float* __restrict__ bih1, const float* __restrict__ bhh1,
    const float* __restrict__ Wst, const float* __restrict__ watt,
    const float* __restrict__ Wout, const float* __restrict__ bout,
    float* __restrict__ out)
{
    extern __shared__ float smdyn[];
    float* Wsm  = smdyn;            // 32768 : 32 gate-rows x 1024 (wih|whh concat)
    float* acts = Wsm + 32768;      // 4224  : 32 x 132 activation chunk (also gls reuse)
    float* gbuf = acts + 4224;      // 528   : 16 x 33 gate pre-activations
    float* h1s  = gbuf + 528;       // 512
    float* sps  = h1s + 512;        // 512
    float* was  = sps + 512;        // 512
    float* evals = was + 512;       // 64
    float* red  = evals + 64;       // 64 (scratch)

    int tid = threadIdx.x, blk = blockIdx.x;
    int j0 = blk * 4;
    int b_at = blk & 31, psub = blk >> 5;
    int lane = tid & 31, w = tid >> 5;

    // ---- prologue: load this block's LSTM weights into smem (once) ----
    {
        int rr2 = tid >> 3, seg = tid & 7;          // 32 rows x 8 loaders
        int cell = rr2 >> 4, rr = rr2 & 15, u = rr >> 2, g = rr & 3;
        const float* wih = cell ? wih1 : wih0;
        const float* whh = cell ? whh1 : whh0;
        const float4* si = (const float4*)(wih + (size_t)(g * 512 + j0 + u) * 512);
        const float4* sh = (const float4*)(whh + (size_t)(g * 512 + j0 + u) * 512);
        float4* dst = (float4*)(Wsm + rr2 * 1024);
#pragma unroll
        for (int q = 0; q < 32; q++) {
            int i4 = seg + 8 * q;
            dst[i4] = (i4 < 128) ? si[i4] : sh[i4 - 128];
        }
    }
    for (int i = tid; i < 512; i += NTHR) was[i] = watt[i];
    __syncthreads();

    unsigned ep = 0;
    int b = tid & 31, r = tid >> 5;     // lstm mapping
    int sb = tid >> 3, smi = tid & 7;   // act staging mapping

    for (int t = 0; t < NSTEPS; t++) {
        int cur = t & 1, nxt = cur ^ 1;

        // ================= LSTM cells =================
#pragma unroll 1
        for (int cell = 0; cell < 2; cell++) {
            const float* xin = cell ? g_h0[nxt] : (g_x + (size_t)t * BB * RR);
            const float* hin = cell ? g_h1[cur] : g_h0[cur];
            float* hout = cell ? g_h1[nxt] : g_h0[nxt];
            float* cst  = cell ? g_c1 : g_c0;
            const float* bi = cell ? bih1 : bih0;
            const float* bh = cell ? bhh1 : bhh0;

            int uA = r >> 2, gA = r & 3;
            int rowA = gA * 512 + j0 + uA;
            int rowB = gA * 512 + j0 + uA + 2;
            float accA = bi[rowA] + bh[rowA];
            float accB = bi[rowB] + bh[rowB];
            const float* WA = Wsm + (cell * 16 + r) * 1024;
            const float* WB = Wsm + (cell * 16 + r + 8) * 1024;

#pragma unroll 1
            for (int ch = 0; ch < 8; ch++) {
                int col0 = (ch & 3) * 128;
                const float* src = (ch < 4) ? xin : hin;
                int wo = (ch < 4) ? 0 : 512;
                __syncthreads();
                {
                    const float4* s4 = (const float4*)(src + sb * 512 + col0);
                    float* arow = acts + sb * 132;
#pragma unroll
                    for (int q = 0; q < 4; q++) {
                        int i4 = smi + 8 * q;
                        *(float4*)&arow[i4 << 2] = s4[i4];
                    }
                }
                __syncthreads();
                const float* ab = acts + b * 132;
                const float* wa = WA + wo + col0;
                const float* wb = WB + wo + col0;
#pragma unroll
                for (int kk = 0; kk < 128; kk += 4) {
                    float4 a4 = *(const float4*)&ab[kk];
                    float4 w1 = *(const float4*)&wa[kk];
                    float4 w2 = *(const float4*)&wb[kk];
                    accA += a4.x * w1.x + a4.y * w1.y + a4.z * w1.z + a4.w * w1.w;
                    accB += a4.x * w2.x + a4.y * w2.y + a4.z * w2.z + a4.w * w2.w;
                }
            }
            gbuf[r * 33 + b] = accA;
            gbuf[(r + 8) * 33 + b] = accB;
            __syncthreads();
            if (tid < 128) {
                int u = tid >> 5, b2 = tid & 31;
                float ai = gbuf[(u * 4 + 0) * 33 + b2];
                float af = gbuf[(u * 4 + 1) * 33 + b2];
                float ag = gbuf[(u * 4 + 2) * 33 + b2];
                float ao = gbuf[(u * 4 + 3) * 33 + b2];
                float si2 = 1.f / (1.f + __expf(-ai));
                float sf  = 1.f / (1.f + __expf(-af));
                float so  = 1.f / (1.f + __expf(-ao));
                float tg  = tanhf(ag);
                int o = b2 * 512 + j0 + u;
                float cn = sf * cst[o] + si2 * tg;
                cst[o] = cn;
                hout[o] = so * tanhf(cn);
            }
            grid_bar(++ep);
        }

        // ================= sp = h1 @ Wst^T (block computes 128 rows) =================
        {
            const float* h1g = g_h1[nxt] + b_at * 512;
            for (int i = tid; i < 512; i += NTHR) h1s[i] = h1g[i];
            __syncthreads();
#pragma unroll 1
            for (int rr = 0; rr < 16; rr++) {
                int a = psub * 128 + w * 16 + rr;
                const float4* wr = (const float4*)(Wst + (size_t)a * 512);
                float s = 0.f;
#pragma unroll
                for (int i = 0; i < 4; i++) {
                    int k4 = lane + 32 * i;
                    float4 v = wr[k4];
                    const float* hh = &h1s[k4 << 2];
                    s += v.x * hh[0] + v.y * hh[1] + v.z * hh[2] + v.w * hh[3];
                }
                s = wredsum(s);
                if (lane == 0) g_sp[b_at * 512 + a] = s;
            }
            grid_bar(++ep);
        }

        // ================= score + exp + partial glimpse (64 p's per block) ==========
        {
            for (int i = tid; i < 512; i += NTHR) sps[i] = g_sp[b_at * 512 + i];
            __syncthreads();
            float psum_local = 0.f;
#pragma unroll 1
            for (int pi = 0; pi < 8; pi++) {
                int p = psub * 64 + w * 8 + pi;
                const float4* fr = (const float4*)(g_fp + ((size_t)b_at * PP + p) * AA);
                float s = 0.f;
#pragma unroll
                for (int i = 0; i < 4; i++) {
                    int k4 = lane + 32 * i;
                    float4 v = fr[k4];
                    float4 sp4 = *(const float4*)&sps[k4 << 2];
                    float4 wa4 = *(const float4*)&was[k4 << 2];
                    s += tanh_fast(v.x + sp4.x) * wa4.x;
                    s += tanh_fast(v.y + sp4.y) * wa4.y;
                    s += tanh_fast(v.z + sp4.z) * wa4.z;
                    s += tanh_fast(v.w + sp4.w) * wa4.w;
                }
                s = wredsum(s);
                if (lane == 0) {
                    float e = __expf(s);      // scores bounded (|s| <= sum|w_att|): no max needed
                    evals[w * 8 + pi] = e;
                    psum_local += e;
                }
            }
            if (lane == 0) red[w] = psum_local;
            __syncthreads();
            if (tid == 0) {
                float s2 = 0.f;
                for (int i = 0; i < 8; i++) s2 += red[i];
                g_psum[b_at * 4 + psub] = s2;
            }
            // partial glimpse over this block's 64 p's for ALL 512 channels
#pragma unroll 1
            for (int c2 = 0; c2 < 2; c2++) {
                int c = w * 64 + (lane << 1) + c2;
                const float4* fr = (const float4*)(feat + ((size_t)b_at * CF + c) * PP + psub * 64);
                float s = 0.f;
#pragma unroll
                for (int q = 0; q < 16; q++) {
                    float4 v = fr[q];
                    s += v.x * evals[q * 4] + v.y * evals[q * 4 + 1]
                       + v.z * evals[q * 4 + 2] + v.w * evals[q * 4 + 3];
                }
                g_glp[((size_t)b_at * 4 + psub) * CF + c] = s;
            }
            grid_bar(++ep);
        }

        // ================= logits (28 vocab rows per block) ==========================
        {
            float ssum = g_psum[b_at * 4 + 0] + g_psum[b_at * 4 + 1]
                       + g_psum[b_at * 4 + 2] + g_psum[b_at * 4 + 3];
            float inv = 1.f / ssum;
            float* gls = acts;   // reuse
            for (int i = tid; i < 512; i += NTHR) {
                float v = 0.f;
#pragma unroll
                for (int ps = 0; ps < 4; ps++) v += g_glp[((size_t)b_at * 4 + ps) * CF + i];
                gls[i] = v * inv;
            }
            __syncthreads();
            int vbase = psub * 28;
            int vend = (vbase + 28 < VV1) ? vbase + 28 : VV1;
#pragma unroll 1
            for (int v = vbase + w; v < vend; v += 8) {
                const float4* wr = (const float4*)(Wout + (size_t)v * 1024);
                float s = 0.f;
#pragma unroll
                for (int i = 0; i < 8; i++) {
                    int k4 = lane + 32 * i;
                    float4 q = wr[k4];
                    const float* sv = (k4 < 128) ? &h1s[k4 << 2] : &gls[(k4 - 128) << 2];
                    s += q.x * sv[0] + q.y * sv[1] + q.z * sv[2] + q.w * sv[3];
                }
                s = wredsum(s);
                if (lane == 0) out[((size_t)b_at * NSTEPS + t) * VV1 + v] = s + bout[v];
            }
            // no barrier: next lstm0 writes only h0[cur]/c0 (not read by logits)
        }
    }
}

// ---------------- launch ----------------
extern "C" void kernel_launch(void* const* d_in, const int* in_sizes, int n_in,
                              void* d_out, int out_size) {
    (void)in_sizes; (void)n_in; (void)out_size;
    const float* features = (const float*)d_in[0];
    const int*   gt       = (const int*)d_in[2];
    const float* W_feat   = (const float*)d_in[3];
    const float* b_feat   = (const float*)d_in[4];
    const float* W_state  = (const float*)d_in[5];
    const float* w_att    = (const float*)d_in[6];
    const float* W_embed  = (const float*)d_in[7];
    const float* wih0     = (const float*)d_in[8];
    const float* whh0     = (const float*)d_in[9];
    const float* bih0     = (const float*)d_in[10];
    const float* bhh0     = (const float*)d_in[11];
    const float* wih1     = (const float*)d_in[12];
    const float* whh1     = (const float*)d_in[13];
    const float* bih1     = (const float*)d_in[14];
    const float* bhh1     = (const float*)d_in[15];
    const float* W_out    = (const float*)d_in[16];
    const float* b_out    = (const float*)d_in[17];
    float* out = (float*)d_out;

    static const int SMEM_BYTES = (32768 + 4224 + 528 + 512 + 512 + 512 + 64 + 64) * 4;
    cudaFuncSetAttribute(k_decode, cudaFuncAttributeMaxDynamicSharedMemorySize, SMEM_BYTES);

    k_init<<<1984, 256>>>(gt, W_embed);
    k_conv<<<dim3(8, 2, 32), 256>>>(features, W_feat, b_feat);
    k_decode<<<NBLK, NTHR, SMEM_BYTES>>>(features,
                                         wih0, whh0, bih0, bhh0,
                                         wih1, whh1, bih1, bhh1,
                                         W_state, w_att, W_out, b_out, out);
}

// round 5
// speedup vs baseline: 2.8992x; 1.3798x over previous
#include <cuda_runtime.h>
#include <cuda_bf16.h>
#include <cstdint>

#define BB      32
#define HH      8
#define WW2     32
#define PP      256
#define CF      512
#define AA      512
#define RR      512
#define VV1     111
#define NSTEPS  31
#define NBLK    128
#define NTHR    256

// padded feature dims (channel-last)
#define PY      10
#define PX      34

// ---------------- device scratch ----------------
__device__ float g_fp[(size_t)BB * PP * AA];    // feat_proj [b][p][a]
__device__ float g_x[(size_t)NSTEPS * BB * RR]; // embeddings [t][b][r]
__device__ float g_h0[2][BB * RR];
__device__ float g_h1[2][BB * RR];
__device__ float g_c0[BB * RR];
__device__ float g_c1[BB * RR];
__device__ float g_sp[BB * AA];
__device__ float g_glp[(size_t)BB * 4 * CF];
__device__ float g_psum[BB * 4];
__device__ unsigned g_cnt;
__device__ unsigned g_gen;

// bf16 split operands for tensor-core conv
__device__ __nv_bfloat16 g_fa_hi[(size_t)BB * PY * PX * CF];
__device__ __nv_bfloat16 g_fa_lo[(size_t)BB * PY * PX * CF];
__device__ __nv_bfloat16 g_wb_hi[(size_t)9 * AA * CF];
__device__ __nv_bfloat16 g_wb_lo[(size_t)9 * AA * CF];

__device__ __forceinline__ float tanh_fast(float x) {
    float y;
    asm("tanh.approx.f32 %0, %1;" : "=f"(y) : "f"(x));
    return y;
}

__device__ __forceinline__ float wredsum(float s) {
#pragma unroll
    for (int o = 16; o; o >>= 1) s += __shfl_xor_sync(0xffffffffu, s, o);
    return s;
}

__device__ __forceinline__ void grid_bar(unsigned ep) {
    __syncthreads();
    if (threadIdx.x == 0) {
        __threadfence();
        unsigned old = atomicAdd(&g_cnt, 1u);
        if (old == NBLK - 1) {
            g_cnt = 0;
            __threadfence();
            *(volatile unsigned*)&g_gen = ep;
        } else {
            while (*(volatile unsigned*)&g_gen < ep) __nanosleep(64);
        }
        __threadfence();
    }
    __syncthreads();
}

__device__ __forceinline__ uint32_t smem_u32(const void* p) {
    uint32_t a;
    asm("{ .reg .u64 t; cvta.to.shared.u64 t, %1; cvt.u32.u64 %0, t; }" : "=r"(a) : "l"(p));
    return a;
}

// SW128(row*128 + c) == row*128 + (c ^ ((row&7)<<4))  for c < 128
#define SW128(o) ((o) ^ (((o) >> 3) & 0x70))

__device__ __forceinline__ void cp16(uint32_t s, const void* g) {
    asm volatile("cp.async.cg.shared.global [%0], [%1], 16;" :: "r"(s), "l"(g) : "memory");
}

#define LDSM4(r, addr) \
    asm volatile("ldmatrix.sync.aligned.m8n8.x4.shared.b16 {%0,%1,%2,%3}, [%4];" \
        : "=r"((r)[0]), "=r"((r)[1]), "=r"((r)[2]), "=r"((r)[3]) : "r"(addr))

#define MMA16816(d, a, b) \
    asm volatile("mma.sync.aligned.m16n8k16.row.col.f32.bf16.bf16.f32 " \
        "{%0,%1,%2,%3}, {%4,%5,%6,%7}, {%8,%9}, {%0,%1,%2,%3};" \
        : "+f"((d)[0]), "+f"((d)[1]), "+f"((d)[2]), "+f"((d)[3]) \
        : "r"((a)[0]), "r"((a)[1]), "r"((a)[2]), "r"((a)[3]), "r"((b)[0]), "r"((b)[1]))

// ---------------- init ----------------
__global__ void k_init(const int* __restrict__ gt, const float* __restrict__ W_embed) {
    int idx = blockIdx.x * 256 + threadIdx.x;
    if (idx == 0) { g_cnt = 0; g_gen = 0; }
    if (idx < BB * RR) {
        g_h0[0][idx] = 0.f;
        g_h1[0][idx] = 0.f;
        g_c0[idx] = 0.f;
        g_c1[idx] = 0.f;
    }
    if (idx < NSTEPS * BB * RR) {
        int t = idx / (BB * RR);
        int rem = idx - t * (BB * RR);
        int b = rem >> 9;
        int r = rem & 511;
        float v = 0.f;
        if (t > 0) {
            int g = gt[b * NSTEPS + t - 1];
            v = W_embed[r * VV1 + g];
        }
        g_x[idx] = v;
    }
}

// ---------------- prep: zero padded bf16 feature arrays ----------------
__global__ void k_zero_pad() {
    size_t n = (size_t)BB * PY * PX * CF / 2;
    uint32_t* a = (uint32_t*)g_fa_hi;
    uint32_t* b = (uint32_t*)g_fa_lo;
    for (size_t i = blockIdx.x * 256 + threadIdx.x; i < n; i += (size_t)gridDim.x * 256) {
        a[i] = 0u;
        b[i] = 0u;
    }
}

// ---------------- prep: transpose features -> padded channel-last hi/lo ----------------
__global__ void k_prep_feat(const float* __restrict__ feat) {
    __shared__ float sm[32][33];
    int pblk = blockIdx.x, c0 = blockIdx.y * 32, b = blockIdx.z;
    int tx = threadIdx.x, ty = threadIdx.y;
    sm[ty][tx] = feat[((size_t)b * CF + c0 + ty) * PP + pblk * 32 + tx];
    __syncthreads();
    int c = c0 + tx;
    float v = sm[tx][ty];
    __nv_bfloat16 hi = __float2bfloat16(v);
    __nv_bfloat16 lo = __float2bfloat16(v - __bfloat162float(hi));
    size_t o = (((size_t)b * PY + (pblk + 1)) * PX + (ty + 1)) * CF + c;
    g_fa_hi[o] = hi;
    g_fa_lo[o] = lo;
}

// ---------------- prep: weights -> [tap][a][c] hi/lo ----------------
__global__ void k_prep_w(const float* __restrict__ Wf) {
    __shared__ float wrow[CF * 9];
    int a = blockIdx.x, tid = threadIdx.x;
    for (int i = tid; i < CF * 9; i += 256) wrow[i] = Wf[(size_t)a * CF * 9 + i];
    __syncthreads();
    for (int tap = 0; tap < 9; tap++) {
        for (int c = tid; c < CF; c += 256) {
            float v = wrow[c * 9 + tap];
            __nv_bfloat16 hi = __float2bfloat16(v);
            __nv_bfloat16 lo = __float2bfloat16(v - __bfloat162float(hi));
            size_t o = ((size_t)tap * AA + a) * CF + c;
            g_wb_hi[o] = hi;
            g_wb_lo[o] = lo;
        }
    }
}

// ---------------- tensor-core conv via mma.sync bf16 (3-term split) ----------------
// 256 CTAs: Mtile = bx>>2 (128 positions), Ntile = bx&3 (128 out-chans).
// 8 warps, warp tile 64x32. K = 9 taps x 512 ch; chunk 64, cp.async double buffer.
#define CSTAGE 65536             // Ahi 16K | Alo 16K | Bhi 16K | Blo 16K
#define CONV_SMEM (2 * CSTAGE + 1024)

__global__ void __launch_bounds__(256) k_conv_mma(const float* __restrict__ bfeat) {
    extern __shared__ char dsm[];
    uint32_t sb = (smem_u32(dsm) + 1023) & ~1023u;

    int tid = threadIdx.x;
    int lane = tid & 31, wid = tid >> 5;
    int warp_m = wid & 1, warp_n = wid >> 1;   // 2 x 4 warps

    int Ntile = blockIdx.x & 3;
    int Mtile = blockIdx.x >> 2;
    int n0 = Ntile * 128;
    int b = Mtile >> 1;
    int p0 = (Mtile & 1) * 128;

    // loader geometry: 2 threads per 128B row
    int arow = tid >> 1, ahalf = tid & 1;
    int p = p0 + arow;
    int ay = p >> 5, ax = p & 31;

    // fragment address constants
    int kh_a = lane >> 4;                    // A k-halves
    int row_l = lane & 15;
    uint32_t aoff[4];
    uint32_t axorm[4];
#pragma unroll
    for (int mi = 0; mi < 4; mi++) {
        int row = warp_m * 64 + mi * 16 + row_l;
        aoff[mi] = row * 128;
        axorm[mi] = (row & 7) << 4;
    }
    int kh_b = (lane >> 3) & 1;
    int n_l = (lane & 7) + ((lane >> 4) << 3);
    uint32_t boff[2], bxorm[2];
#pragma unroll
    for (int np = 0; np < 2; np++) {
        int n = warp_n * 32 + np * 16 + n_l;
        boff[np] = n * 128;
        bxorm[np] = (n & 7) << 4;
    }

    float acc[4][4][4];
#pragma unroll
    for (int mi = 0; mi < 4; mi++)
#pragma unroll
        for (int ni = 0; ni < 4; ni++)
#pragma unroll
            for (int q = 0; q < 4; q++) acc[mi][ni][q] = 0.f;

    auto issue_chunk = [&](int chunk, int st) {
        int tap = chunk >> 3, cblk = chunk & 7;
        int ky = tap / 3, kx = tap - ky * 3;
        uint32_t sbase = sb + st * CSTAGE;
        size_t ga = (((size_t)b * PY + (ay + ky)) * PX + (ax + kx)) * CF
                  + cblk * 64 + ahalf * 32;
        size_t gb = ((size_t)tap * AA + n0 + arow) * CF + cblk * 64 + ahalf * 32;
        const char* pahi = (const char*)(g_fa_hi + ga);
        const char* palo = (const char*)(g_fa_lo + ga);
        const char* pbhi = (const char*)(g_wb_hi + gb);
        const char* pblo = (const char*)(g_wb_lo + gb);
#pragma unroll
        for (int q = 0; q < 4; q++) {
            uint32_t off = arow * 128 + ahalf * 64 + q * 16;
            uint32_t sw = SW128(off);
            cp16(sbase + sw,          pahi + q * 16);
            cp16(sbase + 16384 + sw,  palo + q * 16);
            cp16(sbase + 32768 + sw,  pbhi + q * 16);
            cp16(sbase + 49152 + sw,  pblo + q * 16);
        }
        asm volatile("cp.async.commit_group;" ::: "memory");
    };

    issue_chunk(0, 0);

#pragma unroll 1
    for (int it = 0; it < 72; it++) {
        int st = it & 1;
        asm volatile("cp.async.wait_group 0;" ::: "memory");
        __syncthreads();
        if (it + 1 < 72) issue_chunk(it + 1, st ^ 1);

        uint32_t Ab = sb + st * CSTAGE;
        uint32_t Bb = Ab + 32768;
#pragma unroll
        for (int ks = 0; ks < 4; ks++) {
            uint32_t ahi[4][4], alo[4][4], bhi[4][2], blo[4][2];
            uint32_t kca = ks * 32 + kh_a * 16;
            uint32_t kcb = ks * 32 + kh_b * 16;
#pragma unroll
            for (int mi = 0; mi < 4; mi++) {
                uint32_t ad = Ab + aoff[mi] + (kca ^ axorm[mi]);
                LDSM4(ahi[mi], ad);
                LDSM4(alo[mi], ad + 16384);
            }
#pragma unroll
            for (int np = 0; np < 2; np++) {
                uint32_t bd = Bb + boff[np] + (kcb ^ bxorm[np]);
                uint32_t r[4];
                LDSM4(r, bd);
                bhi[np * 2][0] = r[0]; bhi[np * 2][1] = r[1];
                bhi[np * 2 + 1][0] = r[2]; bhi[np * 2 + 1][1] = r[3];
                LDSM4(r, bd + 16384);
                blo[np * 2][0] = r[0]; blo[np * 2][1] = r[1];
                blo[np * 2 + 1][0] = r[2]; blo[np * 2 + 1][1] = r[3];
            }
#pragma unroll
            for (int mi = 0; mi < 4; mi++)
#pragma unroll
                for (int ni = 0; ni < 4; ni++) {
                    MMA16816(acc[mi][ni], ahi[mi], bhi[ni]);
                    MMA16816(acc[mi][ni], ahi[mi], blo[ni]);
                    MMA16816(acc[mi][ni], alo[mi], bhi[ni]);
                }
        }
    }

    // epilogue: direct stores with bias
    int rgrp = lane >> 2, cpair = (lane & 3) * 2;
    float bs0[4], bs1[4];
#pragma unroll
    for (int ni = 0; ni < 4; ni++) {
        int a = n0 + warp_n * 32 + ni * 8 + cpair;
        bs0[ni] = bfeat[a];
        bs1[ni] = bfeat[a + 1];
    }
#pragma unroll
    for (int mi = 0; mi < 4; mi++) {
#pragma unroll
        for (int h = 0; h < 2; h++) {
            int m = Mtile * 128 + warp_m * 64 + mi * 16 + rgrp + h * 8;
            int obb = m >> 8, op = m & 255;
            float* dst = g_fp + ((size_t)obb * PP + op) * AA + n0 + warp_n * 32;
#pragma unroll
            for (int ni = 0; ni < 4; ni++) {
                float2 v;
                v.x = acc[mi][ni][h * 2 + 0] + bs0[ni];
                v.y = acc[mi][ni][h * 2 + 1] + bs1[ni];
                *(float2*)(dst + ni * 8 + cpair) = v;
            }
        }
    }
}

// ---------------- persistent decode (unchanged from R3 passing version) ----------------
__global__ void __launch_bounds__(NTHR) k_decode(
    const float* __restrict__ feat,
    const float* __restrict__ wih0, const float* __restrict__ whh0,
    const float* __restrict__ bih0, const float* __restrict__ bhh0,
    const float* __restrict__ wih1, const float* __restrict__ whh1,
    const float* __restrict__ bih1, const float* __restrict__ bhh1,
    const float* __restrict__ Wst, const float* __restrict__ watt,
    const float* __restrict__ Wout, const float* __restrict__ bout,
    float* __restrict__ out)
{
    extern __shared__ float smdyn[];
    float* Wsm  = smdyn;
    float* acts = Wsm + 32768;
    float* gbuf = acts + 4224;
    float* h1s  = gbuf + 528;
    float* sps  = h1s + 512;
    float* was  = sps + 512;
    float* evals = was + 512;
    float* red  = evals + 64;

    int tid = threadIdx.x, blk = blockIdx.x;
    int j0 = blk * 4;
    int b_at = blk & 31, psub = blk >> 5;
    int lane = tid & 31, w = tid >> 5;

    {
        int rr2 = tid >> 3, seg = tid & 7;
        int cell = rr2 >> 4, rr = rr2 & 15, u = rr >> 2, g = rr & 3;
        const float* wih = cell ? wih1 : wih0;
        const float* whh = cell ? whh1 : whh0;
        const float4* si = (const float4*)(wih + (size_t)(g * 512 + j0 + u) * 512);
        const float4* sh = (const float4*)(whh + (size_t)(g * 512 + j0 + u) * 512);
        float4* dst = (float4*)(Wsm + rr2 * 1024);
#pragma unroll
        for (int q = 0; q < 32; q++) {
            int i4 = seg + 8 * q;
            dst[i4] = (i4 < 128) ? si[i4] : sh[i4 - 128];
        }
    }
    for (int i = tid; i < 512; i += NTHR) was[i] = watt[i];
    __syncthreads();

    unsigned ep = 0;
    int b = tid & 31, r = tid >> 5;
    int sb = tid >> 3, smi = tid & 7;

    for (int t = 0; t < NSTEPS; t++) {
        int cur = t & 1, nxt = cur ^ 1;

#pragma unroll 1
        for (int cell = 0; cell < 2; cell++) {
            const float* xin = cell ? g_h0[nxt] : (g_x + (size_t)t * BB * RR);
            const float* hin = cell ? g_h1[cur] : g_h0[cur];
            float* hout = cell ? g_h1[nxt] : g_h0[nxt];
            float* cst  = cell ? g_c1 : g_c0;
            const float* bi = cell ? bih1 : bih0;
            const float* bh = cell ? bhh1 : bhh0;

            int uA = r >> 2, gA = r & 3;
            int rowA = gA * 512 + j0 + uA;
            int rowB = gA * 512 + j0 + uA + 2;
            float accA = bi[rowA] + bh[rowA];
            float accB = bi[rowB] + bh[rowB];
            const float* WA = Wsm + (cell * 16 + r) * 1024;
            const float* WB = Wsm + (cell * 16 + r + 8) * 1024;

#pragma unroll 1
            for (int ch = 0; ch < 8; ch++) {
                int col0 = (ch & 3) * 128;
                const float* src = (ch < 4) ? xin : hin;
                int wo = (ch < 4) ? 0 : 512;
                __syncthreads();
                {
                    const float4* s4 = (const float4*)(src + sb * 512 + col0);
                    float* arow = acts + sb * 132;
#pragma unroll
                    for (int q = 0; q < 4; q++) {
                        int i4 = smi + 8 * q;
                        *(float4*)&arow[i4 << 2] = s4[i4];
                    }
                }
                __syncthreads();
                const float* ab = acts + b * 132;
                const float* wa = WA + wo + col0;
                const float* wb = WB + wo + col0;
#pragma unroll
                for (int kk = 0; kk < 128; kk += 4) {
                    float4 a4 = *(const float4*)&ab[kk];
                    float4 w1 = *(const float4*)&wa[kk];
                    float4 w2 = *(const float4*)&wb[kk];
                    accA += a4.x * w1.x + a4.y * w1.y + a4.z * w1.z + a4.w * w1.w;
                    accB += a4.x * w2.x + a4.y * w2.y + a4.z * w2.z + a4.w * w2.w;
                }
            }
            gbuf[r * 33 + b] = accA;
            gbuf[(r + 8) * 33 + b] = accB;
            __syncthreads();
            if (tid < 128) {
                int u = tid >> 5, b2 = tid & 31;
                float ai = gbuf[(u * 4 + 0) * 33 + b2];
                float af = gbuf[(u * 4 + 1) * 33 + b2];
                float ag = gbuf[(u * 4 + 2) * 33 + b2];
                float ao = gbuf[(u * 4 + 3) * 33 + b2];
                float si2 = 1.f / (1.f + __expf(-ai));
                float sf  = 1.f / (1.f + __expf(-af));
                float so  = 1.f / (1.f + __expf(-ao));
                float tg  = tanhf(ag);
                int o = b2 * 512 + j0 + u;
                float cn = sf * cst[o] + si2 * tg;
                cst[o] = cn;
                hout[o] = so * tanhf(cn);
            }
            grid_bar(++ep);
        }

        {
            const float* h1g = g_h1[nxt] + b_at * 512;
            for (int i = tid; i < 512; i += NTHR) h1s[i] = h1g[i];
            __syncthreads();
#pragma unroll 1
            for (int rr = 0; rr < 16; rr++) {
                int a = psub * 128 + w * 16 + rr;
                const float4* wr = (const float4*)(Wst + (size_t)a * 512);
                float s = 0.f;
#pragma unroll
                for (int i = 0; i < 4; i++) {
                    int k4 = lane + 32 * i;
                    float4 v = wr[k4];
                    const float* hh = &h1s[k4 << 2];
                    s += v.x * hh[0] + v.y * hh[1] + v.z * hh[2] + v.w * hh[3];
                }
                s = wredsum(s);
                if (lane == 0) g_sp[b_at * 512 + a] = s;
            }
            grid_bar(++ep);
        }

        {
            for (int i = tid; i < 512; i += NTHR) sps[i] = g_sp[b_at * 512 + i];
            __syncthreads();
            float psum_local = 0.f;
#pragma unroll 1
            for (int pi = 0; pi < 8; pi++) {
                int pq = psub * 64 + w * 8 + pi;
                const float4* fr = (const float4*)(g_fp + ((size_t)b_at * PP + pq) * AA);
                float s = 0.f;
#pragma unroll
                for (int i = 0; i < 4; i++) {
                    int k4 = lane + 32 * i;
                    float4 v = fr[k4];
                    float4 sp4 = *(const float4*)&sps[k4 << 2];
                    float4 wa4 = *(const float4*)&was[k4 << 2];
                    s += tanh_fast(v.x + sp4.x) * wa4.x;
                    s += tanh_fast(v.y + sp4.y) * wa4.y;
                    s += tanh_fast(v.z + sp4.z) * wa4.z;
                    s += tanh_fast(v.w + sp4.w) * wa4.w;
                }
                s = wredsum(s);
                if (lane == 0) {
                    float e = __expf(s);
                    evals[w * 8 + pi] = e;
                    psum_local += e;
                }
            }
            if (lane == 0) red[w] = psum_local;
            __syncthreads();
            if (tid == 0) {
                float s2 = 0.f;
                for (int i = 0; i < 8; i++) s2 += red[i];
                g_psum[b_at * 4 + psub] = s2;
            }
#pragma unroll 1
            for (int c2 = 0; c2 < 2; c2++) {
                int c = w * 64 + (lane << 1) + c2;
                const float4* fr = (const float4*)(feat + ((size_t)b_at * CF + c) * PP + psub * 64);
                float s = 0.f;
#pragma unroll
                for (int q = 0; q < 16; q++) {
                    float4 v = fr[q];
                    s += v.x * evals[q * 4] + v.y * evals[q * 4 + 1]
                       + v.z * evals[q * 4 + 2] + v.w * evals[q * 4 + 3];
                }
                g_glp[((size_t)b_at * 4 + psub) * CF + c] = s;
            }
            grid_bar(++ep);
        }

        {
            float ssum = g_psum[b_at * 4 + 0] + g_psum[b_at * 4 + 1]
                       + g_psum[b_at * 4 + 2] + g_psum[b_at * 4 + 3];
            float inv = 1.f / ssum;
            float* gls = acts;
            for (int i = tid; i < 512; i += NTHR) {
                float v = 0.f;
#pragma unroll
                for (int ps = 0; ps < 4; ps++) v += g_glp[((size_t)b_at * 4 + ps) * CF + i];
                gls[i] = v * inv;
            }
            __syncthreads();
            int vbase = psub * 28;
            int vend = (vbase + 28 < VV1) ? vbase + 28 : VV1;
#pragma unroll 1
            for (int v = vbase + w; v < vend; v += 8) {
                const float4* wr = (const float4*)(Wout + (size_t)v * 1024);
                float s = 0.f;
#pragma unroll
                for (int i = 0; i < 8; i++) {
                    int k4 = lane + 32 * i;
                    float4 q = wr[k4];
                    const float* sv = (k4 < 128) ? &h1s[k4 << 2] : &gls[(k4 - 128) << 2];
                    s += q.x * sv[0] + q.y * sv[1] + q.z * sv[2] + q.w * sv[3];
                }
                s = wredsum(s);
                if (lane == 0) out[((size_t)b_at * NSTEPS + t) * VV1 + v] = s + bout[v];
            }
        }
    }
}

// ---------------- launch ----------------
extern "C" void kernel_launch(void* const* d_in, const int* in_sizes, int n_in,
                              void* d_out, int out_size) {
    (void)in_sizes; (void)n_in; (void)out_size;
    const float* features = (const float*)d_in[0];
    const int*   gt       = (const int*)d_in[2];
    const float* W_feat   = (const float*)d_in[3];
    const float* b_feat   = (const float*)d_in[4];
    const float* W_state  = (const float*)d_in[5];
    const float* w_att    = (const float*)d_in[6];
    const float* W_embed  = (const float*)d_in[7];
    const float* wih0     = (const float*)d_in[8];
    const float* whh0     = (const float*)d_in[9];
    const float* bih0     = (const float*)d_in[10];
    const float* bhh0     = (const float*)d_in[11];
    const float* wih1     = (const float*)d_in[12];
    const float* whh1     = (const float*)d_in[13];
    const float* bih1     = (const float*)d_in[14];
    const float* bhh1     = (const float*)d_in[15];
    const float* W_out    = (const float*)d_in[16];
    const float* b_out    = (const float*)d_in[17];
    float* out = (float*)d_out;

    static const int DEC_SMEM = (32768 + 4224 + 528 + 512 + 512 + 512 + 64 + 64) * 4;
    cudaFuncSetAttribute(k_decode, cudaFuncAttributeMaxDynamicSharedMemorySize, DEC_SMEM);
    cudaFuncSetAttribute(k_conv_mma, cudaFuncAttributeMaxDynamicSharedMemorySize, CONV_SMEM);

    k_init<<<1984, 256>>>(gt, W_embed);
    k_zero_pad<<<512, 256>>>();
    k_prep_feat<<<dim3(8, 16, 32), dim3(32, 32)>>>(features);
    k_prep_w<<<512, 256>>>(W_feat);
    k_conv_mma<<<256, 256, CONV_SMEM>>>(b_feat);
    k_decode<<<NBLK, NTHR, DEC_SMEM>>>(features,
                                       wih0, whh0, bih0, bhh0,
                                       wih1, whh1, bih1, bhh1,
                                       W_state, w_att, W_out, b_out, out);
}

// round 6
// speedup vs baseline: 3.0746x; 1.0605x over previous
#include <cuda_runtime.h>
#include <cuda_bf16.h>
#include <cstdint>

#define BB      32
#define HH      8
#define WW2     32
#define PP      256
#define CF      512
#define AA      512
#define RR      512
#define VV1     111
#define NSTEPS  31
#define NBLK    128
#define NTHR    256

#define PY      10
#define PX      34

// ---------------- device scratch ----------------
__device__ float g_fp[(size_t)BB * PP * AA];
__device__ float g_x[(size_t)NSTEPS * BB * RR];
__device__ float g_h0[2][BB * RR];
__device__ float g_h1[2][BB * RR];
__device__ float g_c0[BB * RR];
__device__ float g_c1[BB * RR];
__device__ float g_sp[BB * AA];
__device__ float g_glp[(size_t)BB * 4 * CF];
__device__ float g_psum[BB * 4];
__device__ unsigned g_cnt;
__device__ unsigned g_gen;
__device__ unsigned g_lbar[32];

__device__ __nv_bfloat16 g_fa_hi[(size_t)BB * PY * PX * CF];
__device__ __nv_bfloat16 g_fa_lo[(size_t)BB * PY * PX * CF];
__device__ __nv_bfloat16 g_wb_hi[(size_t)9 * AA * CF];
__device__ __nv_bfloat16 g_wb_lo[(size_t)9 * AA * CF];

__device__ __forceinline__ float tanh_fast(float x) {
    float y;
    asm("tanh.approx.f32 %0, %1;" : "=f"(y) : "f"(x));
    return y;
}

__device__ __forceinline__ float wredsum(float s) {
#pragma unroll
    for (int o = 16; o; o >>= 1) s += __shfl_xor_sync(0xffffffffu, s, o);
    return s;
}

__device__ __forceinline__ void grid_bar(unsigned ep) {
    __syncthreads();
    if (threadIdx.x == 0) {
        __threadfence();
        unsigned old = atomicAdd(&g_cnt, 1u);
        if (old == NBLK - 1) {
            g_cnt = 0;
            __threadfence();
            *(volatile unsigned*)&g_gen = ep;
        } else {
            while (*(volatile unsigned*)&g_gen < ep) { }
        }
        __threadfence();
    }
    __syncthreads();
}

// 4-block group barrier (groups disjoint by b_at), monotonic counter
__device__ __forceinline__ void group_bar(int grp, unsigned target) {
    __syncthreads();
    if (threadIdx.x == 0) {
        __threadfence();
        atomicAdd(&g_lbar[grp], 1u);
        while (*(volatile unsigned*)&g_lbar[grp] < target) { }
        __threadfence();
    }
    __syncthreads();
}

__device__ __forceinline__ uint32_t smem_u32(const void* p) {
    uint32_t a;
    asm("{ .reg .u64 t; cvta.to.shared.u64 t, %1; cvt.u32.u64 %0, t; }" : "=r"(a) : "l"(p));
    return a;
}

#define SW128(o) ((o) ^ (((o) >> 3) & 0x70))

__device__ __forceinline__ void cp16(uint32_t s, const void* g) {
    asm volatile("cp.async.cg.shared.global [%0], [%1], 16;" :: "r"(s), "l"(g) : "memory");
}

#define LDSM4(r, addr) \
    asm volatile("ldmatrix.sync.aligned.m8n8.x4.shared.b16 {%0,%1,%2,%3}, [%4];" \
        : "=r"((r)[0]), "=r"((r)[1]), "=r"((r)[2]), "=r"((r)[3]) : "r"(addr))

#define MMA16816(d, a, b) \
    asm volatile("mma.sync.aligned.m16n8k16.row.col.f32.bf16.bf16.f32 " \
        "{%0,%1,%2,%3}, {%4,%5,%6,%7}, {%8,%9}, {%0,%1,%2,%3};" \
        : "+f"((d)[0]), "+f"((d)[1]), "+f"((d)[2]), "+f"((d)[3]) \
        : "r"((a)[0]), "r"((a)[1]), "r"((a)[2]), "r"((a)[3]), "r"((b)[0]), "r"((b)[1]))

#define FMA2(acc, w, aa) \
    asm("fma.rn.f32x2 %0, %1, %2, %0;" : "+l"(acc) : "l"(w), "l"(aa))

#define PACK2(aa, f) \
    do { uint32_t _u = __float_as_uint(f); \
         asm("mov.b64 %0, {%1, %1};" : "=l"(aa) : "r"(_u)); } while (0)

// ---------------- init ----------------
__global__ void k_init(const int* __restrict__ gt, const float* __restrict__ W_embed) {
    int idx = blockIdx.x * 256 + threadIdx.x;
    if (idx == 0) { g_cnt = 0; g_gen = 0; }
    if (idx < 32) g_lbar[idx] = 0;
    if (idx < BB * RR) {
        g_h0[0][idx] = 0.f;
        g_h1[0][idx] = 0.f;
        g_c0[idx] = 0.f;
        g_c1[idx] = 0.f;
    }
    if (idx < NSTEPS * BB * RR) {
        int t = idx / (BB * RR);
        int rem = idx - t * (BB * RR);
        int b = rem >> 9;
        int r = rem & 511;
        float v = 0.f;
        if (t > 0) {
            int g = gt[b * NSTEPS + t - 1];
            v = W_embed[r * VV1 + g];
        }
        g_x[idx] = v;
    }
}

// ---------------- conv prep kernels (unchanged from R5) ----------------
__global__ void k_zero_pad() {
    size_t n = (size_t)BB * PY * PX * CF / 2;
    uint32_t* a = (uint32_t*)g_fa_hi;
    uint32_t* b = (uint32_t*)g_fa_lo;
    for (size_t i = blockIdx.x * 256 + threadIdx.x; i < n; i += (size_t)gridDim.x * 256) {
        a[i] = 0u;
        b[i] = 0u;
    }
}

__global__ void k_prep_feat(const float* __restrict__ feat) {
    __shared__ float sm[32][33];
    int pblk = blockIdx.x, c0 = blockIdx.y * 32, b = blockIdx.z;
    int tx = threadIdx.x, ty = threadIdx.y;
    sm[ty][tx] = feat[((size_t)b * CF + c0 + ty) * PP + pblk * 32 + tx];
    __syncthreads();
    int c = c0 + tx;
    float v = sm[tx][ty];
    __nv_bfloat16 hi = __float2bfloat16(v);
    __nv_bfloat16 lo = __float2bfloat16(v - __bfloat162float(hi));
    size_t o = (((size_t)b * PY + (pblk + 1)) * PX + (ty + 1)) * CF + c;
    g_fa_hi[o] = hi;
    g_fa_lo[o] = lo;
}

__global__ void k_prep_w(const float* __restrict__ Wf) {
    __shared__ float wrow[CF * 9];
    int a = blockIdx.x, tid = threadIdx.x;
    for (int i = tid; i < CF * 9; i += 256) wrow[i] = Wf[(size_t)a * CF * 9 + i];
    __syncthreads();
    for (int tap = 0; tap < 9; tap++) {
        for (int c = tid; c < CF; c += 256) {
            float v = wrow[c * 9 + tap];
            __nv_bfloat16 hi = __float2bfloat16(v);
            __nv_bfloat16 lo = __float2bfloat16(v - __bfloat162float(hi));
            size_t o = ((size_t)tap * AA + a) * CF + c;
            g_wb_hi[o] = hi;
            g_wb_lo[o] = lo;
        }
    }
}

// ---------------- tensor-core conv (unchanged from R5) ----------------
#define CSTAGE 65536
#define CONV_SMEM (2 * CSTAGE + 1024)

__global__ void __launch_bounds__(256) k_conv_mma(const float* __restrict__ bfeat) {
    extern __shared__ char dsm[];
    uint32_t sb = (smem_u32(dsm) + 1023) & ~1023u;

    int tid = threadIdx.x;
    int lane = tid & 31, wid = tid >> 5;
    int warp_m = wid & 1, warp_n = wid >> 1;

    int Ntile = blockIdx.x & 3;
    int Mtile = blockIdx.x >> 2;
    int n0 = Ntile * 128;
    int b = Mtile >> 1;
    int p0 = (Mtile & 1) * 128;

    int arow = tid >> 1, ahalf = tid & 1;
    int p = p0 + arow;
    int ay = p >> 5, ax = p & 31;

    int kh_a = lane >> 4;
    int row_l = lane & 15;
    uint32_t aoff[4];
    uint32_t axorm[4];
#pragma unroll
    for (int mi = 0; mi < 4; mi++) {
        int row = warp_m * 64 + mi * 16 + row_l;
        aoff[mi] = row * 128;
        axorm[mi] = (row & 7) << 4;
    }
    int kh_b = (lane >> 3) & 1;
    int n_l = (lane & 7) + ((lane >> 4) << 3);
    uint32_t boff[2], bxorm[2];
#pragma unroll
    for (int np = 0; np < 2; np++) {
        int n = warp_n * 32 + np * 16 + n_l;
        boff[np] = n * 128;
        bxorm[np] = (n & 7) << 4;
    }

    float acc[4][4][4];
#pragma unroll
    for (int mi = 0; mi < 4; mi++)
#pragma unroll
        for (int ni = 0; ni < 4; ni++)
#pragma unroll
            for (int q = 0; q < 4; q++) acc[mi][ni][q] = 0.f;

    auto issue_chunk = [&](int chunk, int st) {
        int tap = chunk >> 3, cblk = chunk & 7;
        int ky = tap / 3, kx = tap - ky * 3;
        uint32_t sbase = sb + st * CSTAGE;
        size_t ga = (((size_t)b * PY + (ay + ky)) * PX + (ax + kx)) * CF
                  + cblk * 64 + ahalf * 32;
        size_t gb = ((size_t)tap * AA + n0 + arow) * CF + cblk * 64 + ahalf * 32;
        const char* pahi = (const char*)(g_fa_hi + ga);
        const char* palo = (const char*)(g_fa_lo + ga);
        const char* pbhi = (const char*)(g_wb_hi + gb);
        const char* pblo = (const char*)(g_wb_lo + gb);
#pragma unroll
        for (int q = 0; q < 4; q++) {
            uint32_t off = arow * 128 + ahalf * 64 + q * 16;
            uint32_t sw = SW128(off);
            cp16(sbase + sw,          pahi + q * 16);
            cp16(sbase + 16384 + sw,  palo + q * 16);
            cp16(sbase + 32768 + sw,  pbhi + q * 16);
            cp16(sbase + 49152 + sw,  pblo + q * 16);
        }
        asm volatile("cp.async.commit_group;" ::: "memory");
    };

    issue_chunk(0, 0);

#pragma unroll 1
    for (int it = 0; it < 72; it++) {
        int st = it & 1;
        asm volatile("cp.async.wait_group 0;" ::: "memory");
        __syncthreads();
        if (it + 1 < 72) issue_chunk(it + 1, st ^ 1);

        uint32_t Ab = sb + st * CSTAGE;
        uint32_t Bb = Ab + 32768;
#pragma unroll
        for (int ks = 0; ks < 4; ks++) {
            uint32_t ahi[4][4], alo[4][4], bhi[4][2], blo[4][2];
            uint32_t kca = ks * 32 + kh_a * 16;
            uint32_t kcb = ks * 32 + kh_b * 16;
#pragma unroll
            for (int mi = 0; mi < 4; mi++) {
                uint32_t ad = Ab + aoff[mi] + (kca ^ axorm[mi]);
                LDSM4(ahi[mi], ad);
                LDSM4(alo[mi], ad + 16384);
            }
#pragma unroll
            for (int np = 0; np < 2; np++) {
                uint32_t bd = Bb + boff[np] + (kcb ^ bxorm[np]);
                uint32_t r[4];
                LDSM4(r, bd);
                bhi[np * 2][0] = r[0]; bhi[np * 2][1] = r[1];
                bhi[np * 2 + 1][0] = r[2]; bhi[np * 2 + 1][1] = r[3];
                LDSM4(r, bd + 16384);
                blo[np * 2][0] = r[0]; blo[np * 2][1] = r[1];
                blo[np * 2 + 1][0] = r[2]; blo[np * 2 + 1][1] = r[3];
            }
#pragma unroll
            for (int mi = 0; mi < 4; mi++)
#pragma unroll
                for (int ni = 0; ni < 4; ni++) {
                    MMA16816(acc[mi][ni], ahi[mi], bhi[ni]);
                    MMA16816(acc[mi][ni], ahi[mi], blo[ni]);
                    MMA16816(acc[mi][ni], alo[mi], bhi[ni]);
                }
        }
    }

    int rgrp = lane >> 2, cpair = (lane & 3) * 2;
    float bs0[4], bs1[4];
#pragma unroll
    for (int ni = 0; ni < 4; ni++) {
        int a = n0 + warp_n * 32 + ni * 8 + cpair;
        bs0[ni] = bfeat[a];
        bs1[ni] = bfeat[a + 1];
    }
#pragma unroll
    for (int mi = 0; mi < 4; mi++) {
#pragma unroll
        for (int h = 0; h < 2; h++) {
            int m = Mtile * 128 + warp_m * 64 + mi * 16 + rgrp + h * 8;
            int obb = m >> 8, op = m & 255;
            float* dst = g_fp + ((size_t)obb * PP + op) * AA + n0 + warp_n * 32;
#pragma unroll
            for (int ni = 0; ni < 4; ni++) {
                float2 v;
                v.x = acc[mi][ni][h * 2 + 0] + bs0[ni];
                v.y = acc[mi][ni][h * 2 + 1] + bs1[ni];
                *(float2*)(dst + ni * 8 + cpair) = v;
            }
        }
    }
}

// ---------------- persistent decode: f32x2 LSTM + local barriers ----------------
// 128 blocks x 256 threads, 1 block/SM. Block owns units [4*blk, 4*blk+4), both cells.
// LSTM thread map: lane = batch b, rg = (tid>>5)&3 -> local rows rg*4..rg*4+3, ksp = tid>>7 k-half.
__global__ void __launch_bounds__(NTHR) k_decode(
    const float* __restrict__ feat,
    const float* __restrict__ wih0, const float* __restrict__ whh0,
    const float* __restrict__ bih0, const float* __restrict__ bhh0,
    const float* __restrict__ wih1, const float* __restrict__ whh1,
    const float* __restrict__ bih1, const float* __restrict__ bhh1,
    const float* __restrict__ Wst, const float* __restrict__ watt,
    const float* __restrict__ Wout, const float* __restrict__ bout,
    float* __restrict__ out)
{
    extern __shared__ float smdyn[];
    float* Wsm  = smdyn;             // 32768 : 16 pair-rows x 2048 (k interleaved x2)
    float* acts = Wsm + 32768;       // 16512 : 32 b x 516 (one full source)
    float* gred = acts + 16512;      // 1056  : [2 ksp][16 lr][33]
    float* h1s  = gred + 1056;       // 512
    float* sps  = h1s + 512;         // 512
    float* was  = sps + 512;         // 512
    float* evals = was + 512;        // 64
    float* red  = evals + 64;        // 64
    float* bsum = red + 64;          // 32 : per (cell, lr) bias sums

    int tid = threadIdx.x, blk = blockIdx.x;
    int j0 = blk * 4;
    int b_at = blk & 31, psub = blk >> 5;
    int lane = tid & 31, w = tid >> 5;
    int rg = (tid >> 5) & 3;
    int ksp = tid >> 7;

    // ---- prologue: interleaved weight pairs + bias sums ----
    {
        int pp = tid >> 4, seg = tid & 15;          // 16 pair-rows x 16 loaders
        int cell = pp >> 3, pr = pp & 7;
        int lr0 = 2 * pr, lr1 = 2 * pr + 1;
        int r0 = (lr0 & 3) * 512 + j0 + (lr0 >> 2);
        int r1 = (lr1 & 3) * 512 + j0 + (lr1 >> 2);
        const float* wih = cell ? wih1 : wih0;
        const float* whh = cell ? whh1 : whh0;
        float* dst = Wsm + pp * 2048;
        for (int q = 0; q < 64; q++) {
            int k = seg * 64 + q;
            float w0, w1;
            if (k < 512) {
                w0 = wih[(size_t)r0 * 512 + k];
                w1 = wih[(size_t)r1 * 512 + k];
            } else {
                w0 = whh[(size_t)r0 * 512 + k - 512];
                w1 = whh[(size_t)r1 * 512 + k - 512];
            }
            *(float2*)&dst[k * 2] = make_float2(w0, w1);
        }
    }
    if (tid < 32) {
        int cell = tid >> 4, lr = tid & 15;
        int row = (lr & 3) * 512 + j0 + (lr >> 2);
        bsum[tid] = (cell ? (bih1[row] + bhh1[row]) : (bih0[row] + bhh0[row]));
    }
    for (int i = tid; i < 512; i += NTHR) was[i] = watt[i];
    __syncthreads();

    uint32_t acts_b = smem_u32(acts);
    int sb = tid >> 3, smi = tid & 7;

    unsigned ep = 0;
    unsigned luse = 0;

    for (int t = 0; t < NSTEPS; t++) {
        int cur = t & 1, nxt = cur ^ 1;

        // ================= LSTM cells (f32x2) =================
#pragma unroll 1
        for (int cell = 0; cell < 2; cell++) {
            const float* xin = cell ? g_h0[nxt] : (g_x + (size_t)t * BB * RR);
            const float* hin = cell ? g_h1[cur] : g_h0[cur];
            float* hout = cell ? g_h1[nxt] : g_h0[nxt];
            float* cst  = cell ? g_c1 : g_c0;

            uint64_t acc0 = 0ull, acc1 = 0ull;
            const float* wb = Wsm + (cell * 8 + rg * 2) * 2048;

#pragma unroll 1
            for (int srcsel = 0; srcsel < 2; srcsel++) {
                const float* src = srcsel ? hin : xin;
                __syncthreads();
                // stage full source: 32 b x 512 k via cp.async
                {
                    uint32_t dstb = acts_b + sb * 516 * 4 + smi * 16;
                    const float* gsrc = src + sb * 512 + smi * 4;
#pragma unroll
                    for (int q = 0; q < 16; q++) cp16(dstb + q * 128, gsrc + q * 32);
                    asm volatile("cp.async.commit_group;" ::: "memory");
                    asm volatile("cp.async.wait_group 0;" ::: "memory");
                }
                __syncthreads();

                int k0 = srcsel * 512 + ksp * 256;
                const float* wp0 = wb + k0 * 2;
                const float* wp1 = wp0 + 2048;
                const float* ab = acts + lane * 516 + ksp * 256;
#pragma unroll 8
                for (int kk = 0; kk < 256; kk += 4) {
                    float4 a4 = *(const float4*)&ab[kk];
                    ulonglong2 wA = *(const ulonglong2*)&wp0[kk * 2];
                    ulonglong2 wB = *(const ulonglong2*)&wp0[kk * 2 + 4];
                    ulonglong2 wC = *(const ulonglong2*)&wp1[kk * 2];
                    ulonglong2 wD = *(const ulonglong2*)&wp1[kk * 2 + 4];
                    uint64_t aa;
                    PACK2(aa, a4.x);
                    FMA2(acc0, wA.x, aa); FMA2(acc1, wC.x, aa);
                    PACK2(aa, a4.y);
                    FMA2(acc0, wA.y, aa); FMA2(acc1, wC.y, aa);
                    PACK2(aa, a4.z);
                    FMA2(acc0, wB.x, aa); FMA2(acc1, wD.x, aa);
                    PACK2(aa, a4.w);
                    FMA2(acc0, wB.y, aa); FMA2(acc1, wD.y, aa);
                }
            }

            // k-split partials -> smem
            {
                float* gr = gred + ksp * 528 + (rg * 4) * 33 + lane;
                gr[0]      = __uint_as_float((uint32_t)acc0);
                gr[33]     = __uint_as_float((uint32_t)(acc0 >> 32));
                gr[66]     = __uint_as_float((uint32_t)acc1);
                gr[99]     = __uint_as_float((uint32_t)(acc1 >> 32));
            }
            __syncthreads();
            if (tid < 128) {
                int u = tid >> 5, b2 = tid & 31;
                int lrb = u * 4;
                float ai = gred[(lrb + 0) * 33 + b2] + gred[528 + (lrb + 0) * 33 + b2] + bsum[cell * 16 + lrb + 0];
                float af = gred[(lrb + 1) * 33 + b2] + gred[528 + (lrb + 1) * 33 + b2] + bsum[cell * 16 + lrb + 1];
                float ag = gred[(lrb + 2) * 33 + b2] + gred[528 + (lrb + 2) * 33 + b2] + bsum[cell * 16 + lrb + 2];
                float ao = gred[(lrb + 3) * 33 + b2] + gred[528 + (lrb + 3) * 33 + b2] + bsum[cell * 16 + lrb + 3];
                float si2 = 1.f / (1.f + __expf(-ai));
                float sf  = 1.f / (1.f + __expf(-af));
                float so  = 1.f / (1.f + __expf(-ao));
                float tg  = tanhf(ag);
                int o = b2 * 512 + j0 + u;
                float cn = sf * cst[o] + si2 * tg;
                cst[o] = cn;
                hout[o] = so * tanhf(cn);
            }
            grid_bar(++ep);
        }

        // ================= sp = h1 @ Wst^T (block computes its 128 rows) ==========
        {
            const float* h1g = g_h1[nxt] + b_at * 512;
            for (int i = tid; i < 512; i += NTHR) h1s[i] = h1g[i];
            __syncthreads();
#pragma unroll 1
            for (int rr = 0; rr < 16; rr++) {
                int a = psub * 128 + w * 16 + rr;
                const float4* wr = (const float4*)(Wst + (size_t)a * 512);
                float s = 0.f;
#pragma unroll
                for (int i = 0; i < 4; i++) {
                    int k4 = lane + 32 * i;
                    float4 v = wr[k4];
                    const float* hh = &h1s[k4 << 2];
                    s += v.x * hh[0] + v.y * hh[1] + v.z * hh[2] + v.w * hh[3];
                }
                s = wredsum(s);
                if (lane == 0) g_sp[b_at * 512 + a] = s;
            }
            group_bar(b_at, 4 * (++luse));
        }

        // ================= score + exp + partial glimpse ==========================
        {
            for (int i = tid; i < 512; i += NTHR) sps[i] = g_sp[b_at * 512 + i];
            __syncthreads();
            float psum_local = 0.f;
#pragma unroll 1
            for (int pi = 0; pi < 8; pi++) {
                int pq = psub * 64 + w * 8 + pi;
                const float4* fr = (const float4*)(g_fp + ((size_t)b_at * PP + pq) * AA);
                float s = 0.f;
#pragma unroll
                for (int i = 0; i < 4; i++) {
                    int k4 = lane + 32 * i;
                    float4 v = fr[k4];
                    float4 sp4 = *(const float4*)&sps[k4 << 2];
                    float4 wa4 = *(const float4*)&was[k4 << 2];
                    s += tanh_fast(v.x + sp4.x) * wa4.x;
                    s += tanh_fast(v.y + sp4.y) * wa4.y;
                    s += tanh_fast(v.z + sp4.z) * wa4.z;
                    s += tanh_fast(v.w + sp4.w) * wa4.w;
                }
                s = wredsum(s);
                if (lane == 0) {
                    float e = __expf(s);
                    evals[w * 8 + pi] = e;
                    psum_local += e;
                }
            }
            if (lane == 0) red[w] = psum_local;
            __syncthreads();
            if (tid == 0) {
                float s2 = 0.f;
                for (int i = 0; i < 8; i++) s2 += red[i];
                g_psum[b_at * 4 + psub] = s2;
            }
#pragma unroll 1
            for (int c2 = 0; c2 < 2; c2++) {
                int c = w * 64 + (lane << 1) + c2;
                const float4* fr = (const float4*)(feat + ((size_t)b_at * CF + c) * PP + psub * 64);
                float s = 0.f;
#pragma unroll
                for (int q = 0; q < 16; q++) {
                    float4 v = fr[q];
                    s += v.x * evals[q * 4] + v.y * evals[q * 4 + 1]
                       + v.z * evals[q * 4 + 2] + v.w * evals[q * 4 + 3];
                }
                g_glp[((size_t)b_at * 4 + psub) * CF + c] = s;
            }
            group_bar(b_at, 4 * (++luse));
        }

        // ================= logits ================================================
        {
            float ssum = g_psum[b_at * 4 + 0] + g_psum[b_at * 4 + 1]
                       + g_psum[b_at * 4 + 2] + g_psum[b_at * 4 + 3];
            float inv = 1.f / ssum;
            float* gls = acts;   // reuse (resynced before next staging)
            for (int i = tid; i < 512; i += NTHR) {
                float v = 0.f;
#pragma unroll
                for (int ps = 0; ps < 4; ps++) v += g_glp[((size_t)b_at * 4 + ps) * CF + i];
                gls[i] = v * inv;
            }
            __syncthreads();
            int vbase = psub * 28;
            int vend = (vbase + 28 < VV1) ? vbase + 28 : VV1;
#pragma unroll 1
            for (int v = vbase + w; v < vend; v += 8) {
                const float4* wr = (const float4*)(Wout + (size_t)v * 1024);
                float s = 0.f;
#pragma unroll
                for (int i = 0; i < 8; i++) {
                    int k4 = lane + 32 * i;
                    float4 q = wr[k4];
                    const float* sv = (k4 < 128) ? &h1s[k4 << 2] : &gls[(k4 - 128) << 2];
                    s += q.x * sv[0] + q.y * sv[1] + q.z * sv[2] + q.w * sv[3];
                }
                s = wredsum(s);
                if (lane == 0) out[((size_t)b_at * NSTEPS + t) * VV1 + v] = s + bout[v];
            }
        }
    }
}

// ---------------- launch ----------------
extern "C" void kernel_launch(void* const* d_in, const int* in_sizes, int n_in,
                              void* d_out, int out_size) {
    (void)in_sizes; (void)n_in; (void)out_size;
    const float* features = (const float*)d_in[0];
    const int*   gt       = (const int*)d_in[2];
    const float* W_feat   = (const float*)d_in[3];
    const float* b_feat   = (const float*)d_in[4];
    const float* W_state  = (const float*)d_in[5];
    const float* w_att    = (const float*)d_in[6];
    const float* W_embed  = (const float*)d_in[7];
    const float* wih0     = (const float*)d_in[8];
    const float* whh0     = (const float*)d_in[9];
    const float* bih0     = (const float*)d_in[10];
    const float* bhh0     = (const float*)d_in[11];
    const float* wih1     = (const float*)d_in[12];
    const float* whh1     = (const float*)d_in[13];
    const float* bih1     = (const float*)d_in[14];
    const float* bhh1     = (const float*)d_in[15];
    const float* W_out    = (const float*)d_in[16];
    const float* b_out    = (const float*)d_in[17];
    float* out = (float*)d_out;

    static const int DEC_SMEM = (32768 + 16512 + 1056 + 512 + 512 + 512 + 64 + 64 + 32) * 4;
    cudaFuncSetAttribute(k_decode, cudaFuncAttributeMaxDynamicSharedMemorySize, DEC_SMEM);
    cudaFuncSetAttribute(k_conv_mma, cudaFuncAttributeMaxDynamicSharedMemorySize, CONV_SMEM);

    k_init<<<1984, 256>>>(gt, W_embed);
    k_zero_pad<<<512, 256>>>();
    k_prep_feat<<<dim3(8, 16, 32), dim3(32, 32)>>>(features);
    k_prep_w<<<512, 256>>>(W_feat);
    k_conv_mma<<<256, 256, CONV_SMEM>>>(b_feat);
    k_decode<<<NBLK, NTHR, DEC_SMEM>>>(features,
                                       wih0, whh0, bih0, bhh0,
                                       wih1, whh1, bih1, bhh1,
                                       W_state, w_att, W_out, b_out, out);
}

// round 7
// speedup vs baseline: 4.3480x; 1.4142x over previous
#include <cuda_runtime.h>
#include <cuda_bf16.h>
#include <cstdint>

#define BB      32
#define HH      8
#define WW2     32
#define PP      256
#define CF      512
#define AA      512
#define RR      512
#define VV1     111
#define NSTEPS  31
#define NBLK    128
#define NTHR    256

#define PY      10
#define PX      34

// ---------------- device scratch ----------------
__device__ float g_fp[(size_t)BB * PP * AA];
__device__ float g_x[(size_t)NSTEPS * BB * RR];
__device__ float g_h0[2][BB * RR];
__device__ float g_h1h[32][BB * RR];    // h1 history: slot t+1 = h1(t); slot 0 = zeros
__device__ float g_c0[BB * RR];
__device__ float g_c1[BB * RR];
__device__ unsigned g_cnt;
__device__ unsigned g_gen;

__device__ __nv_bfloat16 g_fa_hi[(size_t)BB * PY * PX * CF];
__device__ __nv_bfloat16 g_fa_lo[(size_t)BB * PY * PX * CF];
__device__ __nv_bfloat16 g_wb_hi[(size_t)9 * AA * CF];
__device__ __nv_bfloat16 g_wb_lo[(size_t)9 * AA * CF];

__device__ __forceinline__ float tanh_fast(float x) {
    float y;
    asm("tanh.approx.f32 %0, %1;" : "=f"(y) : "f"(x));
    return y;
}

__device__ __forceinline__ void grid_bar(unsigned ep) {
    __syncthreads();
    if (threadIdx.x == 0) {
        __threadfence();
        unsigned old = atomicAdd(&g_cnt, 1u);
        if (old == NBLK - 1) {
            g_cnt = 0;
            __threadfence();
            *(volatile unsigned*)&g_gen = ep;
        } else {
            while (*(volatile unsigned*)&g_gen < ep) { }
        }
        __threadfence();
    }
    __syncthreads();
}

__device__ __forceinline__ uint32_t smem_u32(const void* p) {
    uint32_t a;
    asm("{ .reg .u64 t; cvta.to.shared.u64 t, %1; cvt.u32.u64 %0, t; }" : "=r"(a) : "l"(p));
    return a;
}

#define SW128(o) ((o) ^ (((o) >> 3) & 0x70))

__device__ __forceinline__ void cp16(uint32_t s, const void* g) {
    asm volatile("cp.async.cg.shared.global [%0], [%1], 16;" :: "r"(s), "l"(g) : "memory");
}

#define LDSM4(r, addr) \
    asm volatile("ldmatrix.sync.aligned.m8n8.x4.shared.b16 {%0,%1,%2,%3}, [%4];" \
        : "=r"((r)[0]), "=r"((r)[1]), "=r"((r)[2]), "=r"((r)[3]) : "r"(addr))

#define MMA16816(d, a, b) \
    asm volatile("mma.sync.aligned.m16n8k16.row.col.f32.bf16.bf16.f32 " \
        "{%0,%1,%2,%3}, {%4,%5,%6,%7}, {%8,%9}, {%0,%1,%2,%3};" \
        : "+f"((d)[0]), "+f"((d)[1]), "+f"((d)[2]), "+f"((d)[3]) \
        : "r"((a)[0]), "r"((a)[1]), "r"((a)[2]), "r"((a)[3]), "r"((b)[0]), "r"((b)[1]))

#define FMA2(acc, w, aa) \
    asm("fma.rn.f32x2 %0, %1, %2, %0;" : "+l"(acc) : "l"(w), "l"(aa))

#define PACK2(aa, f) \
    do { uint32_t _u = __float_as_uint(f); \
         asm("mov.b64 %0, {%1, %1};" : "=l"(aa) : "r"(_u)); } while (0)

__device__ __forceinline__ unsigned long long wredsum2(unsigned long long v) {
#pragma unroll
    for (int o = 16; o; o >>= 1) {
        unsigned long long u = __shfl_xor_sync(0xffffffffu, v, o);
        asm("add.rn.f32x2 %0, %0, %1;" : "+l"(v) : "l"(u));
    }
    return v;
}

__device__ __forceinline__ float u64lo(unsigned long long v) { return __uint_as_float((uint32_t)v); }
__device__ __forceinline__ float u64hi(unsigned long long v) { return __uint_as_float((uint32_t)(v >> 32)); }

// ---------------- init ----------------
__global__ void k_init(const int* __restrict__ gt, const float* __restrict__ W_embed) {
    int idx = blockIdx.x * 256 + threadIdx.x;
    if (idx == 0) { g_cnt = 0; g_gen = 0; }
    if (idx < BB * RR) {
        g_h0[0][idx] = 0.f;
        g_h0[1][idx] = 0.f;
        g_h1h[0][idx] = 0.f;
        g_c0[idx] = 0.f;
        g_c1[idx] = 0.f;
    }
    if (idx < NSTEPS * BB * RR) {
        int t = idx / (BB * RR);
        int rem = idx - t * (BB * RR);
        int b = rem >> 9;
        int r = rem & 511;
        float v = 0.f;
        if (t > 0) {
            int g = gt[b * NSTEPS + t - 1];
            v = W_embed[r * VV1 + g];
        }
        g_x[idx] = v;
    }
}

// ---------------- conv prep kernels (unchanged) ----------------
__global__ void k_zero_pad() {
    size_t n = (size_t)BB * PY * PX * CF / 2;
    uint32_t* a = (uint32_t*)g_fa_hi;
    uint32_t* b = (uint32_t*)g_fa_lo;
    for (size_t i = blockIdx.x * 256 + threadIdx.x; i < n; i += (size_t)gridDim.x * 256) {
        a[i] = 0u;
        b[i] = 0u;
    }
}

__global__ void k_prep_feat(const float* __restrict__ feat) {
    __shared__ float sm[32][33];
    int pblk = blockIdx.x, c0 = blockIdx.y * 32, b = blockIdx.z;
    int tx = threadIdx.x, ty = threadIdx.y;
    sm[ty][tx] = feat[((size_t)b * CF + c0 + ty) * PP + pblk * 32 + tx];
    __syncthreads();
    int c = c0 + tx;
    float v = sm[tx][ty];
    __nv_bfloat16 hi = __float2bfloat16(v);
    __nv_bfloat16 lo = __float2bfloat16(v - __bfloat162float(hi));
    size_t o = (((size_t)b * PY + (pblk + 1)) * PX + (ty + 1)) * CF + c;
    g_fa_hi[o] = hi;
    g_fa_lo[o] = lo;
}

__global__ void k_prep_w(const float* __restrict__ Wf) {
    __shared__ float wrow[CF * 9];
    int a = blockIdx.x, tid = threadIdx.x;
    for (int i = tid; i < CF * 9; i += 256) wrow[i] = Wf[(size_t)a * CF * 9 + i];
    __syncthreads();
    for (int tap = 0; tap < 9; tap++) {
        for (int c = tid; c < CF; c += 256) {
            float v = wrow[c * 9 + tap];
            __nv_bfloat16 hi = __float2bfloat16(v);
            __nv_bfloat16 lo = __float2bfloat16(v - __bfloat162float(hi));
            size_t o = ((size_t)tap * AA + a) * CF + c;
            g_wb_hi[o] = hi;
            g_wb_lo[o] = lo;
        }
    }
}

// ---------------- tensor-core conv (unchanged from R5/R6) ----------------
#define CSTAGE 65536
#define CONV_SMEM (2 * CSTAGE + 1024)

__global__ void __launch_bounds__(256) k_conv_mma(const float* __restrict__ bfeat) {
    extern __shared__ char dsm[];
    uint32_t sb = (smem_u32(dsm) + 1023) & ~1023u;

    int tid = threadIdx.x;
    int lane = tid & 31, wid = tid >> 5;
    int warp_m = wid & 1, warp_n = wid >> 1;

    int Ntile = blockIdx.x & 3;
    int Mtile = blockIdx.x >> 2;
    int n0 = Ntile * 128;
    int b = Mtile >> 1;
    int p0 = (Mtile & 1) * 128;

    int arow = tid >> 1, ahalf = tid & 1;
    int p = p0 + arow;
    int ay = p >> 5, ax = p & 31;

    int kh_a = lane >> 4;
    int row_l = lane & 15;
    uint32_t aoff[4];
    uint32_t axorm[4];
#pragma unroll
    for (int mi = 0; mi < 4; mi++) {
        int row = warp_m * 64 + mi * 16 + row_l;
        aoff[mi] = row * 128;
        axorm[mi] = (row & 7) << 4;
    }
    int kh_b = (lane >> 3) & 1;
    int n_l = (lane & 7) + ((lane >> 4) << 3);
    uint32_t boff[2], bxorm[2];
#pragma unroll
    for (int np = 0; np < 2; np++) {
        int n = warp_n * 32 + np * 16 + n_l;
        boff[np] = n * 128;
        bxorm[np] = (n & 7) << 4;
    }

    float acc[4][4][4];
#pragma unroll
    for (int mi = 0; mi < 4; mi++)
#pragma unroll
        for (int ni = 0; ni < 4; ni++)
#pragma unroll
            for (int q = 0; q < 4; q++) acc[mi][ni][q] = 0.f;

    auto issue_chunk = [&](int chunk, int st) {
        int tap = chunk >> 3, cblk = chunk & 7;
        int ky = tap / 3, kx = tap - ky * 3;
        uint32_t sbase = sb + st * CSTAGE;
        size_t ga = (((size_t)b * PY + (ay + ky)) * PX + (ax + kx)) * CF
                  + cblk * 64 + ahalf * 32;
        size_t gb = ((size_t)tap * AA + n0 + arow) * CF + cblk * 64 + ahalf * 32;
        const char* pahi = (const char*)(g_fa_hi + ga);
        const char* palo = (const char*)(g_fa_lo + ga);
        const char* pbhi = (const char*)(g_wb_hi + gb);
        const char* pblo = (const char*)(g_wb_lo + gb);
#pragma unroll
        for (int q = 0; q < 4; q++) {
            uint32_t off = arow * 128 + ahalf * 64 + q * 16;
            uint32_t sw = SW128(off);
            cp16(sbase + sw,          pahi + q * 16);
            cp16(sbase + 16384 + sw,  palo + q * 16);
            cp16(sbase + 32768 + sw,  pbhi + q * 16);
            cp16(sbase + 49152 + sw,  pblo + q * 16);
        }
        asm volatile("cp.async.commit_group;" ::: "memory");
    };

    issue_chunk(0, 0);

#pragma unroll 1
    for (int it = 0; it < 72; it++) {
        int st = it & 1;
        asm volatile("cp.async.wait_group 0;" ::: "memory");
        __syncthreads();
        if (it + 1 < 72) issue_chunk(it + 1, st ^ 1);

        uint32_t Ab = sb + st * CSTAGE;
        uint32_t Bb = Ab + 32768;
#pragma unroll
        for (int ks = 0; ks < 4; ks++) {
            uint32_t ahi[4][4], alo[4][4], bhi[4][2], blo[4][2];
            uint32_t kca = ks * 32 + kh_a * 16;
            uint32_t kcb = ks * 32 + kh_b * 16;
#pragma unroll
            for (int mi = 0; mi < 4; mi++) {
                uint32_t ad = Ab + aoff[mi] + (kca ^ axorm[mi]);
                LDSM4(ahi[mi], ad);
                LDSM4(alo[mi], ad + 16384);
            }
#pragma unroll
            for (int np = 0; np < 2; np++) {
                uint32_t bd = Bb + boff[np] + (kcb ^ bxorm[np]);
                uint32_t r[4];
                LDSM4(r, bd);
                bhi[np * 2][0] = r[0]; bhi[np * 2][1] = r[1];
                bhi[np * 2 + 1][0] = r[2]; bhi[np * 2 + 1][1] = r[3];
                LDSM4(r, bd + 16384);
                blo[np * 2][0] = r[0]; blo[np * 2][1] = r[1];
                blo[np * 2 + 1][0] = r[2]; blo[np * 2 + 1][1] = r[3];
            }
#pragma unroll
            for (int mi = 0; mi < 4; mi++)
#pragma unroll
                for (int ni = 0; ni < 4; ni++) {
                    MMA16816(acc[mi][ni], ahi[mi], bhi[ni]);
                    MMA16816(acc[mi][ni], ahi[mi], blo[ni]);
                    MMA16816(acc[mi][ni], alo[mi], bhi[ni]);
                }
        }
    }

    int rgrp = lane >> 2, cpair = (lane & 3) * 2;
    float bs0[4], bs1[4];
#pragma unroll
    for (int ni = 0; ni < 4; ni++) {
        int a = n0 + warp_n * 32 + ni * 8 + cpair;
        bs0[ni] = bfeat[a];
        bs1[ni] = bfeat[a + 1];
    }
#pragma unroll
    for (int mi = 0; mi < 4; mi++) {
#pragma unroll
        for (int h = 0; h < 2; h++) {
            int m = Mtile * 128 + warp_m * 64 + mi * 16 + rgrp + h * 8;
            int obb = m >> 8, op = m & 255;
            float* dst = g_fp + ((size_t)obb * PP + op) * AA + n0 + warp_n * 32;
#pragma unroll
            for (int ni = 0; ni < 4; ni++) {
                float2 v;
                v.x = acc[mi][ni][h * 2 + 0] + bs0[ni];
                v.y = acc[mi][ni][h * 2 + 1] + bs1[ni];
                *(float2*)(dst + ni * 8 + cpair) = v;
            }
        }
    }
}

// ---------------- persistent LSTM-only kernel: 1 grid barrier per step ----------------
// 128 blocks x 256 threads. Block owns units [4*blk, 4*blk+4) for both cells.
// Schedule: cell0(0) | bar | loop t: [cell1(t) ; cell0(t+1)] | bar.
// Staged h0(t) feeds BOTH cell1 x-part and cell0(t+1) h-part.
__global__ void __launch_bounds__(NTHR) k_lstm(
    const float* __restrict__ wih0, const float* __restrict__ whh0,
    const float* __restrict__ bih0, const float* __restrict__ bhh0,
    const float* __restrict__ wih1, const float* __restrict__ whh1,
    const float* __restrict__ bih1, const float* __restrict__ bhh1)
{
    extern __shared__ float smdyn[];
    float* Wsm  = smdyn;             // 32768 : 16 pair-rows x 2048 (k interleaved x2)
    float* acts = Wsm + 32768;       // 16512 : 32 b x 516
    float* gred = acts + 16512;      // 1056  : [2 ksp][16 lr][33]
    float* bsum = gred + 1056;       // 32

    int tid = threadIdx.x, blk = blockIdx.x;
    int j0 = blk * 4;
    int lane = tid & 31;
    int rg = (tid >> 5) & 3;
    int ksp = tid >> 7;

    // prologue: interleaved weight pairs + bias sums (same layout as R6)
    {
        int pp = tid >> 4, seg = tid & 15;
        int cell = pp >> 3, pr = pp & 7;
        int lr0 = 2 * pr, lr1 = 2 * pr + 1;
        int r0 = (lr0 & 3) * 512 + j0 + (lr0 >> 2);
        int r1 = (lr1 & 3) * 512 + j0 + (lr1 >> 2);
        const float* wih = cell ? wih1 : wih0;
        const float* whh = cell ? whh1 : whh0;
        float* dst = Wsm + pp * 2048;
        for (int q = 0; q < 64; q++) {
            int k = seg * 64 + q;
            float w0, w1;
            if (k < 512) {
                w0 = wih[(size_t)r0 * 512 + k];
                w1 = wih[(size_t)r1 * 512 + k];
            } else {
                w0 = whh[(size_t)r0 * 512 + k - 512];
                w1 = whh[(size_t)r1 * 512 + k - 512];
            }
            *(float2*)&dst[k * 2] = make_float2(w0, w1);
        }
    }
    if (tid < 32) {
        int cell = tid >> 4, lr = tid & 15;
        int row = (lr & 3) * 512 + j0 + (lr >> 2);
        bsum[tid] = (cell ? (bih1[row] + bhh1[row]) : (bih0[row] + bhh0[row]));
    }
    __syncthreads();

    uint32_t acts_b = smem_u32(acts);
    int sb = tid >> 3, smi = tid & 7;

    auto stage = [&](const float* src) {
        __syncthreads();
        uint32_t dstb = acts_b + sb * 516 * 4 + smi * 16;
        const float* gsrc = src + sb * 512 + smi * 4;
#pragma unroll
        for (int q = 0; q < 16; q++) cp16(dstb + q * 128, gsrc + q * 32);
        asm volatile("cp.async.commit_group;" ::: "memory");
        asm volatile("cp.async.wait_group 0;" ::: "memory");
        __syncthreads();
    };

    auto accum = [&](int cell, int region, uint64_t& a0, uint64_t& a1) {
        int k0 = region + ksp * 256;
        const float* wp0 = Wsm + (cell * 8 + rg * 2) * 2048 + k0 * 2;
        const float* wp1 = wp0 + 2048;
        const float* ab = acts + lane * 516 + ksp * 256;
#pragma unroll 8
        for (int kk = 0; kk < 256; kk += 4) {
            float4 a4 = *(const float4*)&ab[kk];
            ulonglong2 wA = *(const ulonglong2*)&wp0[kk * 2];
            ulonglong2 wB = *(const ulonglong2*)&wp0[kk * 2 + 4];
            ulonglong2 wC = *(const ulonglong2*)&wp1[kk * 2];
            ulonglong2 wD = *(const ulonglong2*)&wp1[kk * 2 + 4];
            uint64_t aa;
            PACK2(aa, a4.x);
            FMA2(a0, wA.x, aa); FMA2(a1, wC.x, aa);
            PACK2(aa, a4.y);
            FMA2(a0, wA.y, aa); FMA2(a1, wC.y, aa);
            PACK2(aa, a4.z);
            FMA2(a0, wB.x, aa); FMA2(a1, wD.x, aa);
            PACK2(aa, a4.w);
            FMA2(a0, wB.y, aa); FMA2(a1, wD.y, aa);
        }
    };

    auto epilogue = [&](int cell, uint64_t a0, uint64_t a1, float* cst, float* hout) {
        float* gr = gred + ksp * 528 + (rg * 4) * 33 + lane;
        gr[0]  = u64lo(a0);
        gr[33] = u64hi(a0);
        gr[66] = u64lo(a1);
        gr[99] = u64hi(a1);
        __syncthreads();
        if (tid < 128) {
            int u = tid >> 5, b2 = tid & 31;
            int lrb = u * 4;
            float ai = gred[(lrb + 0) * 33 + b2] + gred[528 + (lrb + 0) * 33 + b2] + bsum[cell * 16 + lrb + 0];
            float af = gred[(lrb + 1) * 33 + b2] + gred[528 + (lrb + 1) * 33 + b2] + bsum[cell * 16 + lrb + 1];
            float ag = gred[(lrb + 2) * 33 + b2] + gred[528 + (lrb + 2) * 33 + b2] + bsum[cell * 16 + lrb + 2];
            float ao = gred[(lrb + 3) * 33 + b2] + gred[528 + (lrb + 3) * 33 + b2] + bsum[cell * 16 + lrb + 3];
            float si2 = 1.f / (1.f + __expf(-ai));
            float sf  = 1.f / (1.f + __expf(-af));
            float so  = 1.f / (1.f + __expf(-ao));
            float tg  = tanhf(ag);
            int o = b2 * 512 + j0 + u;
            float cn = sf * cst[o] + si2 * tg;
            cst[o] = cn;
            hout[o] = so * tanhf(cn);
        }
    };

    // ---- cell0 step 0 ----
    {
        uint64_t a0 = 0ull, a1 = 0ull;
        stage(g_x);
        accum(0, 0, a0, a1);
        stage(g_h0[1]);       // zeros (h0(-1))
        accum(0, 512, a0, a1);
        __syncthreads();      // protect gred (none pending) — cheap
        epilogue(0, a0, a1, g_c0, g_h0[0]);
    }
    grid_bar(1);
    unsigned ep = 1;

#pragma unroll 1
    for (int t = 0; t < NSTEPS; t++) {
        int p = t & 1;
        uint64_t c1a0 = 0ull, c1a1 = 0ull;
        uint64_t c0a0 = 0ull, c0a1 = 0ull;

        stage(g_h0[p]);                   // h0(t)
        accum(1, 0, c1a0, c1a1);          // cell1 x-part (wih1 @ h0(t))
        if (t < NSTEPS - 1) accum(0, 512, c0a0, c0a1);  // cell0(t+1) h-part (whh0 @ h0(t))

        stage(g_h1h[t]);                  // h1(t-1)
        accum(1, 512, c1a0, c1a1);        // cell1 h-part
        __syncthreads();
        epilogue(1, c1a0, c1a1, g_c1, g_h1h[t + 1]);

        if (t < NSTEPS - 1) {
            stage(g_x + (size_t)(t + 1) * BB * RR);
            accum(0, 0, c0a0, c0a1);      // cell0 x-part
            __syncthreads();
            epilogue(0, c0a0, c0a1, g_c0, g_h0[p ^ 1]);
        }
        grid_bar(++ep);
    }
}

// ---------------- attention + output: fully parallel over (b, step-group) ----------------
// grid (32 b, 4 tg), 256 threads, no inter-block deps. Each block: 8 steps (last group 7).
// t-pairs packed as f32x2 throughout; plane layouts [tp][dim] for conflict-free LDS.
#define ATT_SMEM 59680

__global__ void __launch_bounds__(NTHR) k_attn(
    const float* __restrict__ feat,
    const float* __restrict__ Wst, const float* __restrict__ watt,
    const float* __restrict__ Wout, const float* __restrict__ bout,
    float* __restrict__ out)
{
    extern __shared__ float asmem[];
    float2* h1p  = (float2*)asmem;       // [4][512]
    float2* spp  = h1p + 2048;           // [4][512]
    float2* attp = spp + 2048;           // [4][256]
    float2* glp  = attp + 1024;          // [4][512]
    float*  was_s = (float*)(glp + 2048);// [512]
    float2* red8p = (float2*)(was_s + 512); // [8][4]
    float2* sinvp = red8p + 32;          // [4]

    int b = blockIdx.x, tg = blockIdx.y;
    int t0 = tg * 8;
    int nt = (t0 + 8 <= NSTEPS) ? 8 : (NSTEPS - t0);
    int tid = threadIdx.x, lane = tid & 31, w = tid >> 5;

    // load h1 pairs + w_att
    for (int i = tid; i < 512; i += NTHR) {
        was_s[i] = watt[i];
#pragma unroll
        for (int tp = 0; tp < 4; tp++) {
            int ja = 2 * tp, jb = 2 * tp + 1;
            float v0 = (ja < nt) ? g_h1h[t0 + ja + 1][b * 512 + i] : 0.f;
            float v1 = (jb < nt) ? g_h1h[t0 + jb + 1][b * 512 + i] : 0.f;
            h1p[tp * 512 + i] = make_float2(v0, v1);
        }
    }
    __syncthreads();

    // ---- sp[t][a] = h1(t) . Wst[a] ----
#pragma unroll 1
    for (int a = w; a < 512; a += 8) {
        uint64_t acc[4] = {0ull, 0ull, 0ull, 0ull};
        const float2* wr = (const float2*)(Wst + (size_t)a * 512);
#pragma unroll
        for (int i = 0; i < 8; i++) {
            int k2 = lane + 32 * i;
            float2 wv = wr[k2];
            uint64_t wp;
#pragma unroll
            for (int tp = 0; tp < 4; tp++) {
                ulonglong2 hq = *(const ulonglong2*)&h1p[tp * 512 + 2 * k2];
                PACK2(wp, wv.x); FMA2(acc[tp], hq.x, wp);
                PACK2(wp, wv.y); FMA2(acc[tp], hq.y, wp);
            }
        }
#pragma unroll
        for (int tp = 0; tp < 4; tp++) acc[tp] = wredsum2(acc[tp]);
        if (lane == 0) {
#pragma unroll
            for (int tp = 0; tp < 4; tp++)
                spp[tp * 512 + a] = make_float2(u64lo(acc[tp]), u64hi(acc[tp]));
        }
    }
    __syncthreads();

    // ---- scores + exp ----
    float wreg[16];
#pragma unroll
    for (int i = 0; i < 8; i++) {
        float2 wv = *(const float2*)&was_s[2 * (lane + 32 * i)];
        wreg[2 * i] = wv.x;
        wreg[2 * i + 1] = wv.y;
    }
    uint64_t ps[4] = {0ull, 0ull, 0ull, 0ull};
#pragma unroll 1
    for (int pq = w; pq < 256; pq += 8) {
        uint64_t sc[4] = {0ull, 0ull, 0ull, 0ull};
        const float2* fr = (const float2*)(g_fp + ((size_t)b * PP + pq) * AA);
#pragma unroll
        for (int i = 0; i < 8; i++) {
            int a2 = lane + 32 * i;
            float2 fv = fr[a2];
            ulonglong2 q0 = *(const ulonglong2*)&spp[0 * 512 + 2 * a2];
            ulonglong2 q1 = *(const ulonglong2*)&spp[1 * 512 + 2 * a2];
            ulonglong2 q2 = *(const ulonglong2*)&spp[2 * 512 + 2 * a2];
            ulonglong2 q3 = *(const ulonglong2*)&spp[3 * 512 + 2 * a2];
            uint64_t wp0, wp1, th;
            PACK2(wp0, wreg[2 * i]);
            PACK2(wp1, wreg[2 * i + 1]);
            uint32_t tl, th2;
            // a = 2*a2 (fv.x):
            tl = __float_as_uint(tanh_fast(fv.x + u64lo(q0.x)));
            th2 = __float_as_uint(tanh_fast(fv.x + u64hi(q0.x)));
            th = (uint64_t)tl | ((uint64_t)th2 << 32); FMA2(sc[0], th, wp0);
            tl = __float_as_uint(tanh_fast(fv.x + u64lo(q1.x)));
            th2 = __float_as_uint(tanh_fast(fv.x + u64hi(q1.x)));
            th = (uint64_t)tl | ((uint64_t)th2 << 32); FMA2(sc[1], th, wp0);
            tl = __float_as_uint(tanh_fast(fv.x + u64lo(q2.x)));
            th2 = __float_as_uint(tanh_fast(fv.x + u64hi(q2.x)));
            th = (uint64_t)tl | ((uint64_t)th2 << 32); FMA2(sc[2], th, wp0);
            tl = __float_as_uint(tanh_fast(fv.x + u64lo(q3.x)));
            th2 = __float_as_uint(tanh_fast(fv.x + u64hi(q3.x)));
            th = (uint64_t)tl | ((uint64_t)th2 << 32); FMA2(sc[3], th, wp0);
            // a = 2*a2+1 (fv.y):
            tl = __float_as_uint(tanh_fast(fv.y + u64lo(q0.y)));
            th2 = __float_as_uint(tanh_fast(fv.y + u64hi(q0.y)));
            th = (uint64_t)tl | ((uint64_t)th2 << 32); FMA2(sc[0], th, wp1);
            tl = __float_as_uint(tanh_fast(fv.y + u64lo(q1.y)));
            th2 = __float_as_uint(tanh_fast(fv.y + u64hi(q1.y)));
            th = (uint64_t)tl | ((uint64_t)th2 << 32); FMA2(sc[1], th, wp1);
            tl = __float_as_uint(tanh_fast(fv.y + u64lo(q2.y)));
            th2 = __float_as_uint(tanh_fast(fv.y + u64hi(q2.y)));
            th = (uint64_t)tl | ((uint64_t)th2 << 32); FMA2(sc[2], th, wp1);
            tl = __float_as_uint(tanh_fast(fv.y + u64lo(q3.y)));
            th2 = __float_as_uint(tanh_fast(fv.y + u64hi(q3.y)));
            th = (uint64_t)tl | ((uint64_t)th2 << 32); FMA2(sc[3], th, wp1);
        }
#pragma unroll
        for (int tp = 0; tp < 4; tp++) sc[tp] = wredsum2(sc[tp]);
        if (lane == 0) {
#pragma unroll
            for (int tp = 0; tp < 4; tp++) {
                float e0 = __expf(u64lo(sc[tp]));
                float e1 = __expf(u64hi(sc[tp]));
                attp[tp * 256 + pq] = make_float2(e0, e1);
                uint64_t ev = (uint64_t)__float_as_uint(e0) | ((uint64_t)__float_as_uint(e1) << 32);
                asm("add.rn.f32x2 %0, %0, %1;" : "+l"(ps[tp]) : "l"(ev));
            }
        }
    }
    if (lane == 0) {
#pragma unroll
        for (int tp = 0; tp < 4; tp++)
            red8p[w * 4 + tp] = make_float2(u64lo(ps[tp]), u64hi(ps[tp]));
    }
    __syncthreads();
    if (tid < 4) {
        float sx = 0.f, sy = 0.f;
#pragma unroll
        for (int ww = 0; ww < 8; ww++) {
            float2 v = red8p[ww * 4 + tid];
            sx += v.x; sy += v.y;
        }
        sinvp[tid] = make_float2(1.f / sx, 1.f / sy);
    }
    __syncthreads();
    for (int pq = tid; pq < 256; pq += NTHR) {
#pragma unroll
        for (int tp = 0; tp < 4; tp++) {
            float2 v = attp[tp * 256 + pq];
            float2 s = sinvp[tp];
            attp[tp * 256 + pq] = make_float2(v.x * s.x, v.y * s.y);
        }
    }
    __syncthreads();

    // ---- glimpse[t][c] = sum_p feat[b][c][p] * att[t][p] ----
#pragma unroll 1
    for (int c = w; c < 512; c += 8) {
        uint64_t gc[4] = {0ull, 0ull, 0ull, 0ull};
        const float2* fr = (const float2*)(feat + ((size_t)b * CF + c) * PP);
#pragma unroll
        for (int i = 0; i < 4; i++) {
            int p2 = lane + 32 * i;
            float2 fv = fr[p2];
            uint64_t fp0, fp1;
            PACK2(fp0, fv.x);
            PACK2(fp1, fv.y);
#pragma unroll
            for (int tp = 0; tp < 4; tp++) {
                ulonglong2 aq = *(const ulonglong2*)&attp[tp * 256 + 2 * p2];
                FMA2(gc[tp], aq.x, fp0);
                FMA2(gc[tp], aq.y, fp1);
            }
        }
#pragma unroll
        for (int tp = 0; tp < 4; tp++) gc[tp] = wredsum2(gc[tp]);
        if (lane == 0) {
#pragma unroll
            for (int tp = 0; tp < 4; tp++)
                glp[tp * 512 + c] = make_float2(u64lo(gc[tp]), u64hi(gc[tp]));
        }
    }
    __syncthreads();

    // ---- logits[t][v] = [h1(t), glimpse(t)] . Wout[v] + b_out[v] ----
#pragma unroll 1
    for (int v = w; v < VV1; v += 8) {
        uint64_t lg[4] = {0ull, 0ull, 0ull, 0ull};
        const float2* wr = (const float2*)(Wout + (size_t)v * 1024);
#pragma unroll
        for (int i = 0; i < 16; i++) {
            int k2 = lane + 32 * i;
            float2 wv = wr[k2];
            const float2* plane = (i < 8) ? h1p : glp;
            int kk = (i < 8) ? (2 * k2) : (2 * (k2 - 256));
            uint64_t wp0, wp1;
            PACK2(wp0, wv.x);
            PACK2(wp1, wv.y);
#pragma unroll
            for (int tp = 0; tp < 4; tp++) {
                ulonglong2 hq = *(const ulonglong2*)&plane[tp * 512 + kk];
                FMA2(lg[tp], hq.x, wp0);
                FMA2(lg[tp], hq.y, wp1);
            }
        }
#pragma unroll
        for (int tp = 0; tp < 4; tp++) lg[tp] = wredsum2(lg[tp]);
        if (lane == 0) {
            float bv = bout[v];
#pragma unroll
            for (int tp = 0; tp < 4; tp++) {
                int ja = 2 * tp, jb = 2 * tp + 1;
                if (ja < nt) out[((size_t)b * NSTEPS + t0 + ja) * VV1 + v] = u64lo(lg[tp]) + bv;
                if (jb < nt) out[((size_t)b * NSTEPS + t0 + jb) * VV1 + v] = u64hi(lg[tp]) + bv;
            }
        }
    }
}

// ---------------- launch ----------------
extern "C" void kernel_launch(void* const* d_in, const int* in_sizes, int n_in,
                              void* d_out, int out_size) {
    (void)in_sizes; (void)n_in; (void)out_size;
    const float* features = (const float*)d_in[0];
    const int*   gt       = (const int*)d_in[2];
    const float* W_feat   = (const float*)d_in[3];
    const float* b_feat   = (const float*)d_in[4];
    const float* W_state  = (const float*)d_in[5];
    const float* w_att    = (const float*)d_in[6];
    const float* W_embed  = (const float*)d_in[7];
    const float* wih0     = (const float*)d_in[8];
    const float* whh0     = (const float*)d_in[9];
    const float* bih0     = (const float*)d_in[10];
    const float* bhh0     = (const float*)d_in[11];
    const float* wih1     = (const float*)d_in[12];
    const float* whh1     = (const float*)d_in[13];
    const float* bih1     = (const float*)d_in[14];
    const float* bhh1     = (const float*)d_in[15];
    const float* W_out    = (const float*)d_in[16];
    const float* b_out    = (const float*)d_in[17];
    float* out = (float*)d_out;

    static const int DEC_SMEM = (32768 + 16512 + 1056 + 32) * 4;
    cudaFuncSetAttribute(k_lstm, cudaFuncAttributeMaxDynamicSharedMemorySize, DEC_SMEM);
    cudaFuncSetAttribute(k_conv_mma, cudaFuncAttributeMaxDynamicSharedMemorySize, CONV_SMEM);
    cudaFuncSetAttribute(k_attn, cudaFuncAttributeMaxDynamicSharedMemorySize, ATT_SMEM);

    k_init<<<1984, 256>>>(gt, W_embed);
    k_zero_pad<<<512, 256>>>();
    k_prep_feat<<<dim3(8, 16, 32), dim3(32, 32)>>>(features);
    k_prep_w<<<512, 256>>>(W_feat);
    k_conv_mma<<<256, 256, CONV_SMEM>>>(b_feat);
    k_lstm<<<NBLK, NTHR, DEC_SMEM>>>(wih0, whh0, bih0, bhh0,
                                     wih1, whh1, bih1, bhh1);
    k_attn<<<dim3(32, 4), NTHR, ATT_SMEM>>>(features, W_state, w_att, W_out, b_out, out);
}